// round 12
// baseline (speedup 1.0000x reference)
#include <cuda_runtime.h>
#include <cuda_bf16.h>
#include <cstdint>

#define Sdim 2048
#define Bdim 32
#define Hdim 512
#define Gdim 2048   // 4*H
#define NCTA_REC 64

typedef unsigned long long ull;

// ---------------- scratch (module-load allocated) ----------------
__device__ float g_xg [(size_t)Sdim * Bdim * Gdim];               // [s*B+b][4H]
__device__ __align__(16) __nv_bfloat16 g_Ahi [(size_t)Sdim * Bdim * Hdim];
__device__ __align__(16) __nv_bfloat16 g_Alo [(size_t)Sdim * Bdim * Hdim];
__device__ __align__(16) __nv_bfloat16 g_h1hi[(size_t)Sdim * Bdim * Hdim];
__device__ __align__(16) __nv_bfloat16 g_h1lo[(size_t)Sdim * Bdim * Hdim];
__device__ __align__(16) __nv_bfloat16 g_Whi [2 * (size_t)Gdim * Hdim];
__device__ __align__(16) __nv_bfloat16 g_Wlo [2 * (size_t)Gdim * Hdim];
__device__ __align__(16) __nv_bfloat16 g_hb_hi[2][Bdim * Hdim];   // ping-pong h split
__device__ __align__(16) __nv_bfloat16 g_hb_lo[2][Bdim * Hdim];
__device__ unsigned g_cnt;
__device__ unsigned g_gen;

// ---------------- PTX helpers ----------------
__device__ __forceinline__ uint32_t smem_u32(const void* p) {
    uint32_t a;
    asm("{ .reg .u64 t; cvta.to.shared.u64 t, %1; cvt.u32.u64 %0, t; }" : "=r"(a) : "l"(p));
    return a;
}
#define CP_ASYNC16(dst, src) \
    asm volatile("cp.async.cg.shared.global [%0], [%1], 16;" :: "r"(dst), "l"(src))
#define CP_COMMIT() asm volatile("cp.async.commit_group;" ::: "memory")
#define CP_WAIT1()  asm volatile("cp.async.wait_group 1;" ::: "memory")
#define CP_WAIT0()  asm volatile("cp.async.wait_group 0;" ::: "memory")

__device__ __forceinline__ void ldm_x4(uint32_t* r, uint32_t addr) {
    asm volatile("ldmatrix.sync.aligned.m8n8.x4.shared.b16 {%0,%1,%2,%3}, [%4];"
                 : "=r"(r[0]), "=r"(r[1]), "=r"(r[2]), "=r"(r[3]) : "r"(addr));
}
__device__ __forceinline__ void mma_bf16(float* d, const uint32_t* a, const uint32_t* b) {
    asm volatile(
        "mma.sync.aligned.m16n8k16.row.col.f32.bf16.bf16.f32 "
        "{%0,%1,%2,%3}, {%4,%5,%6,%7}, {%8,%9}, {%0,%1,%2,%3};"
        : "+f"(d[0]), "+f"(d[1]), "+f"(d[2]), "+f"(d[3])
        : "r"(a[0]), "r"(a[1]), "r"(a[2]), "r"(a[3]), "r"(b[0]), "r"(b[1]));
}

// ---------------- grid barrier (validated R1/R4/R6; replay-safe) ----------------
__device__ __forceinline__ void grid_barrier() {
    __syncthreads();
    if (threadIdx.x == 0) {
        __threadfence();
        unsigned gen = *(volatile unsigned*)&g_gen;
        unsigned old = atomicAdd(&g_cnt, 1u);
        if (old == gridDim.x - 1) {
            atomicExch(&g_cnt, 0u);
            __threadfence();
            atomicAdd(&g_gen, 1u);
        } else {
            while (*(volatile unsigned*)&g_gen == gen) { __nanosleep(32); }
        }
        __threadfence();
    }
    __syncthreads();
}

// ---------------- fp32 -> bf16 hi/lo split ----------------
__device__ __forceinline__ void split4(float4 v, ull& hi, ull& lo) {
    union { __nv_bfloat16 h[4]; ull u; } H, L;
    float f[4] = {v.x, v.y, v.z, v.w};
#pragma unroll
    for (int i = 0; i < 4; i++) {
        __nv_bfloat16 a = __float2bfloat16_rn(f[i]);
        H.h[i] = a;
        L.h[i] = __float2bfloat16_rn(f[i] - __bfloat162float(a));
    }
    hi = H.u; lo = L.u;
}

// X[b][s][k] -> g_Ahi/g_Alo[(s*B+b)][k]
__global__ __launch_bounds__(256) void conv_x_kernel(const float* __restrict__ X) {
    size_t i = (size_t)blockIdx.x * 256 + threadIdx.x;
    int row = (int)(i >> 7);
    int c4  = (int)(i & 127);
    int b = row & 31, s = row >> 5;
    float4 v = __ldg((const float4*)(X + ((size_t)b * Sdim + s) * Hdim + c4 * 4));
    ull hi, lo;
    split4(v, hi, lo);
    *(ull*)(g_Ahi + (size_t)row * Hdim + c4 * 4) = hi;
    *(ull*)(g_Alo + (size_t)row * Hdim + c4 * 4) = lo;
}

// Wih[2][4H][H] -> g_Whi/g_Wlo
__global__ __launch_bounds__(256) void conv_w_kernel(const float* __restrict__ W) {
    size_t i = (size_t)blockIdx.x * 256 + threadIdx.x;
    float4 v = __ldg((const float4*)W + i);
    ull hi, lo;
    split4(v, hi, lo);
    *(ull*)(g_Whi + i * 4) = hi;
    *(ull*)(g_Wlo + i * 4) = lo;
}

// ---------------- mma.sync split-bf16 GEMM (validated R4) ----------------
#define TSTRIDE 80
#define MAT_B   (128 * TSTRIDE)
#define STAGE_B (4 * MAT_B)

__global__ __launch_bounds__(256, 1) void gemm_mma_kernel(
    int src_h1, int layer,
    const float* __restrict__ bih, const float* __restrict__ bhh)
{
    extern __shared__ char smem[];
    uint32_t sb = smem_u32(smem);
    int tid = threadIdx.x, wid = tid >> 5, lane = tid & 31;
    int col0 = blockIdx.x * 128;
    int row0 = blockIdx.y * 128;
    int wm = wid & 1, wn = wid >> 1;

    const __nv_bfloat16* a0p = (src_h1 ? g_h1hi : g_Ahi) + (size_t)row0 * Hdim;
    const __nv_bfloat16* a1p = (src_h1 ? g_h1lo : g_Alo) + (size_t)row0 * Hdim;
    const __nv_bfloat16* w0p = g_Whi + (size_t)layer * Gdim * Hdim + (size_t)col0 * Hdim;
    const __nv_bfloat16* w1p = g_Wlo + (size_t)layer * Gdim * Hdim + (size_t)col0 * Hdim;

    int ldr  = tid >> 2;
    int ldkc = tid & 3;

#define PREFETCH(stg, k0)                                                         \
    do {                                                                          \
        _Pragma("unroll")                                                         \
        for (int m = 0; m < 4; m++) {                                             \
            const __nv_bfloat16* mp = (m == 0 ? a0p : m == 1 ? a1p :              \
                                       m == 2 ? w0p : w1p);                       \
            _Pragma("unroll")                                                     \
            for (int i = 0; i < 2; i++) {                                         \
                int r = ldr + i * 64;                                             \
                uint32_t dst = sb + (stg) * STAGE_B + m * MAT_B +                 \
                               r * TSTRIDE + ldkc * 16;                           \
                const void* srcp = mp + (size_t)r * Hdim + (k0) + ldkc * 8;       \
                CP_ASYNC16(dst, srcp);                                            \
            }                                                                     \
        }                                                                         \
        CP_COMMIT();                                                              \
    } while (0)

    float acc[4][4][4];
#pragma unroll
    for (int i = 0; i < 4; i++)
#pragma unroll
        for (int j = 0; j < 4; j++)
#pragma unroll
            for (int k = 0; k < 4; k++) acc[i][j][k] = 0.0f;

    PREFETCH(0, 0);
    PREFETCH(1, 32);

    int tile = lane >> 3, trow = lane & 7;

    for (int kt = 0; kt < 16; kt++) {
        if (kt == 15) CP_WAIT0(); else CP_WAIT1();
        __syncthreads();
        uint32_t base = sb + (kt & 1) * STAGE_B;

#pragma unroll
        for (int ks = 0; ks < 2; ks++) {
            uint32_t ahi[4][4], alo[4][4];
#pragma unroll
            for (int mf = 0; mf < 4; mf++) {
                int row = wm * 64 + mf * 16 + (tile & 1) * 8 + trow;
                int col = ks * 16 + (tile >> 1) * 8;
                ldm_x4(ahi[mf], base + 0 * MAT_B + row * TSTRIDE + col * 2);
                ldm_x4(alo[mf], base + 1 * MAT_B + row * TSTRIDE + col * 2);
            }
            uint32_t bhi[4][2], blo[4][2];
#pragma unroll
            for (int p = 0; p < 2; p++) {
                int rn = wn * 32 + p * 16 + (tile >> 1) * 8 + trow;
                int ck = ks * 16 + (tile & 1) * 8;
                uint32_t r4[4];
                ldm_x4(r4, base + 2 * MAT_B + rn * TSTRIDE + ck * 2);
                bhi[2*p][0] = r4[0]; bhi[2*p][1] = r4[1];
                bhi[2*p+1][0] = r4[2]; bhi[2*p+1][1] = r4[3];
                ldm_x4(r4, base + 3 * MAT_B + rn * TSTRIDE + ck * 2);
                blo[2*p][0] = r4[0]; blo[2*p][1] = r4[1];
                blo[2*p+1][0] = r4[2]; blo[2*p+1][1] = r4[3];
            }
#pragma unroll
            for (int mf = 0; mf < 4; mf++)
#pragma unroll
                for (int nf = 0; nf < 4; nf++) {
                    mma_bf16(acc[mf][nf], ahi[mf], bhi[nf]);
                    mma_bf16(acc[mf][nf], ahi[mf], blo[nf]);
                    mma_bf16(acc[mf][nf], alo[mf], bhi[nf]);
                }
        }
        __syncthreads();
        if (kt < 14) PREFETCH(kt & 1, (kt + 2) * 32);
    }

#pragma unroll
    for (int mf = 0; mf < 4; mf++) {
        int r0 = row0 + wm * 64 + mf * 16 + (lane >> 2);
#pragma unroll
        for (int nf = 0; nf < 4; nf++) {
            int cb = col0 + wn * 32 + nf * 8 + 2 * (lane & 3);
            float b0v = __ldg(&bih[cb])     + __ldg(&bhh[cb]);
            float b1v = __ldg(&bih[cb + 1]) + __ldg(&bhh[cb + 1]);
            *(float2*)&g_xg[(size_t)r0 * Gdim + cb] =
                make_float2(acc[mf][nf][0] + b0v, acc[mf][nf][1] + b1v);
            *(float2*)&g_xg[(size_t)(r0 + 8) * Gdim + cb] =
                make_float2(acc[mf][nf][2] + b0v, acc[mf][nf][3] + b1v);
        }
    }
#undef PREFETCH
}

// ---------------- persistent recurrence on tensor cores ----------------
// 64 CTAs x 256 threads. CTA owns 8 hidden units (32 gate cols).
// Whh B-frags in registers (split bf16); h staged split via cp.async each step.
// 8-warp k-split (64 each); smem reduction; 256 threads do activations.
#define RSTRIDE 1040                 // bytes per smem bf16 row of 512 (+8 pad)
#define RED_OFF (64 * RSTRIDE)       // 66560
#define RED_LEN 33                   // floats per red row

__global__ __launch_bounds__(256, 1) void lstm_recur_mma(
    const float* __restrict__ Whh, float* __restrict__ hseq,
    int out_bsh, float* __restrict__ hTo, float* __restrict__ cTo)
{
    extern __shared__ char sm[];
    uint32_t sb = smem_u32(sm);
    uint32_t sHhi = sb;                       // [32 rows] (also W-hi staging at init)
    uint32_t sHlo = sb + 32 * RSTRIDE;        // [32 rows] (also W-lo staging at init)
    float* red = (float*)(sm + RED_OFF);      // [8][32][RED_LEN]

    int tid = threadIdx.x, wid = tid >> 5, lane = tid & 31;
    int b  = tid & 31;
    int jj = tid >> 5;          // 0..7: hidden unit within CTA
    int j0 = blockIdx.x * 8;

    // stage Whh (split bf16) into the H area: row r = q*8 + j  <-  Whh[q*512 + j0 + j]
    for (int idx = tid; idx < 32 * 128; idx += 256) {
        int r = idx >> 7, c4 = idx & 127;
        int q = r >> 3, j = r & 7;
        float4 v = __ldg((const float4*)(Whh + (size_t)(q * Hdim + j0 + j) * Hdim + c4 * 4));
        ull hi, lo;
        split4(v, hi, lo);
        *(ull*)(sm + r * RSTRIDE + c4 * 8) = hi;
        *(ull*)(sm + 32 * RSTRIDE + r * RSTRIDE + c4 * 8) = lo;
    }
    // h(0) = 0 (64 CTAs x 256 threads cover all 32x512)
    g_hb_hi[0][b * Hdim + j0 + jj] = __float2bfloat16(0.0f);
    g_hb_lo[0][b * Hdim + j0 + jj] = __float2bfloat16(0.0f);
    __syncthreads();

    // preload B fragments: warp w owns k in [w*64, w*64+64); N=32 gate cols
    int kbase = wid * 64;
    int tile = lane >> 3, trow = lane & 7;
    uint32_t bhi[4][4][2], blo[4][4][2];
#pragma unroll
    for (int kt = 0; kt < 4; kt++) {
#pragma unroll
        for (int p = 0; p < 2; p++) {
            int rn = p * 16 + (tile >> 1) * 8 + trow;
            int ck = kbase + kt * 16 + (tile & 1) * 8;
            uint32_t r4[4];
            ldm_x4(r4, sHhi + rn * RSTRIDE + ck * 2);
            bhi[kt][2*p][0] = r4[0]; bhi[kt][2*p][1] = r4[1];
            bhi[kt][2*p+1][0] = r4[2]; bhi[kt][2*p+1][1] = r4[3];
            ldm_x4(r4, sHlo + rn * RSTRIDE + ck * 2);
            blo[kt][2*p][0] = r4[0]; blo[kt][2*p][1] = r4[1];
            blo[kt][2*p+1][0] = r4[2]; blo[kt][2*p+1][1] = r4[3];
        }
    }
    grid_barrier();   // h(0) visible; W-frag reads done before H reuses the area

    float c_st = 0.0f;
    const float* xg_base = g_xg + (size_t)b * Gdim + (j0 + jj);

    for (int t = 0; t < Sdim; t++) {
        int cur = t & 1;
        float x_i = __ldg(xg_base + 0 * Hdim);
        float x_f = __ldg(xg_base + 1 * Hdim);
        float x_g = __ldg(xg_base + 2 * Hdim);
        float x_o = __ldg(xg_base + 3 * Hdim);

        // stage h(t-1) split: 2 x 32KB -> smem (barrier at loop end published it)
        const char* srchi = (const char*)g_hb_hi[cur];
        const char* srclo = (const char*)g_hb_lo[cur];
#pragma unroll
        for (int i = 0; i < 8; i++) {
            int idx = tid + i * 256;          // 0..2047 (16B chunks)
            int r = idx >> 6, ch = idx & 63;
            CP_ASYNC16(sHhi + r * RSTRIDE + ch * 16, srchi + idx * 16);
            CP_ASYNC16(sHlo + r * RSTRIDE + ch * 16, srclo + idx * 16);
        }
        CP_COMMIT();
        CP_WAIT0();
        __syncthreads();

        // MMA: [32 x 64-slice] x [64-slice x 32] partials
        float acc[2][4][4];
#pragma unroll
        for (int i = 0; i < 2; i++)
#pragma unroll
            for (int j = 0; j < 4; j++)
#pragma unroll
                for (int k = 0; k < 4; k++) acc[i][j][k] = 0.0f;

#pragma unroll
        for (int kt = 0; kt < 4; kt++) {
            int colb = kbase + kt * 16 + (tile >> 1) * 8;
            uint32_t ahi[2][4], alo[2][4];
#pragma unroll
            for (int mf = 0; mf < 2; mf++) {
                int row = mf * 16 + (tile & 1) * 8 + trow;
                ldm_x4(ahi[mf], sHhi + row * RSTRIDE + colb * 2);
                ldm_x4(alo[mf], sHlo + row * RSTRIDE + colb * 2);
            }
#pragma unroll
            for (int mf = 0; mf < 2; mf++)
#pragma unroll
                for (int nf = 0; nf < 4; nf++) {
                    mma_bf16(acc[mf][nf], ahi[mf], bhi[kt][nf]);
                    mma_bf16(acc[mf][nf], ahi[mf], blo[kt][nf]);
                    mma_bf16(acc[mf][nf], alo[mf], bhi[kt][nf]);
                }
        }

        // per-warp partials -> red[wid][m 0..31][n 0..31]
#pragma unroll
        for (int mf = 0; mf < 2; mf++)
#pragma unroll
            for (int nf = 0; nf < 4; nf++) {
                int row = mf * 16 + (lane >> 2);
                int col = nf * 8 + (lane & 3) * 2;
                float* p0 = red + ((wid * 32 + row) * RED_LEN + col);
                p0[0] = acc[mf][nf][0]; p0[1] = acc[mf][nf][1];
                float* p1 = red + ((wid * 32 + row + 8) * RED_LEN + col);
                p1[0] = acc[mf][nf][2]; p1[1] = acc[mf][nf][3];
            }
        __syncthreads();

        // all 256 threads: (b, jj) activation + state update
        {
            float di = x_i, df = x_f, dg = x_g, do_ = x_o;
#pragma unroll
            for (int w = 0; w < 8; w++) {
                const float* rr = red + (w * 32 + b) * RED_LEN;
                di  += rr[0 * 8 + jj];
                df  += rr[1 * 8 + jj];
                dg  += rr[2 * 8 + jj];
                do_ += rr[3 * 8 + jj];
            }
            float ig = 1.0f / (1.0f + __expf(-di));
            float fg = 1.0f / (1.0f + __expf(-df));
            float gg = tanhf(dg);
            float og = 1.0f / (1.0f + __expf(-do_));
            c_st = fg * c_st + ig * gg;
            float h = og * tanhf(c_st);

            __nv_bfloat16 hh = __float2bfloat16_rn(h);
            __nv_bfloat16 hl = __float2bfloat16_rn(h - __bfloat162float(hh));
            g_hb_hi[cur ^ 1][b * Hdim + j0 + jj] = hh;
            g_hb_lo[cur ^ 1][b * Hdim + j0 + jj] = hl;
            if (out_bsh) {
                hseq[((size_t)b * Sdim + t) * Hdim + j0 + jj] = h;
                if (hTo && t == Sdim - 1) {
                    hTo[b * Hdim + j0 + jj] = h;
                    cTo[b * Hdim + j0 + jj] = c_st;
                }
            } else {
                size_t r = ((size_t)t * Bdim + b) * Hdim + j0 + jj;
                g_h1hi[r] = hh;
                g_h1lo[r] = hl;
            }
        }
        grid_barrier();   // publishes h(t); isolates red / sH reuse

        xg_base += (size_t)Bdim * Gdim;
    }
}

// ---------------- launch ----------------
extern "C" void kernel_launch(void* const* d_in, const int* in_sizes, int n_in,
                              void* d_out, int out_size) {
    (void)in_sizes; (void)n_in;
    const float* X   = (const float*)d_in[0];
    const float* Wih = (const float*)d_in[1];
    const float* Whh = (const float*)d_in[2];
    const float* bih = (const float*)d_in[3];
    const float* bhh = (const float*)d_in[4];
    float* out = (float*)d_out;

    size_t ht_elems = (size_t)Bdim * Sdim * Hdim;
    float* hTo = nullptr; float* cTo = nullptr;
    if ((size_t)out_size >= ht_elems + 2 * (size_t)Bdim * Hdim) {
        hTo = out + ht_elems;
        cTo = hTo + (size_t)Bdim * Hdim;
    }

    const int smem_rec  = RED_OFF + 8 * 32 * RED_LEN * 4;   // 66560 + 33792 = 100352
    const int smem_gemm = 2 * STAGE_B;                      // 81920
    cudaFuncSetAttribute(lstm_recur_mma,
                         cudaFuncAttributeMaxDynamicSharedMemorySize, smem_rec);
    cudaFuncSetAttribute(gemm_mma_kernel,
                         cudaFuncAttributeMaxDynamicSharedMemorySize, smem_gemm);

    conv_w_kernel<<<2048, 256>>>(Wih);
    conv_x_kernel<<<32768, 256>>>(X);

    dim3 ggrid(Gdim / 128, (Sdim * Bdim) / 128);   // (16, 512)

    // Layer 0
    gemm_mma_kernel<<<ggrid, 256, smem_gemm>>>(0, 0, bih, bhh);
    lstm_recur_mma<<<NCTA_REC, 256, smem_rec>>>(Whh, nullptr, 0, nullptr, nullptr);
    // Layer 1
    gemm_mma_kernel<<<ggrid, 256, smem_gemm>>>(1, 1, bih + Gdim, bhh + Gdim);
    lstm_recur_mma<<<NCTA_REC, 256, smem_rec>>>(Whh + (size_t)Gdim * Hdim,
                                                out, 1, hTo, cTo);
}

// round 13
// speedup vs baseline: 1.2413x; 1.2413x over previous
#include <cuda_runtime.h>
#include <cuda_bf16.h>
#include <cstdint>

#define Sdim 2048
#define Bdim 32
#define Hdim 512
#define Gdim 2048   // 4*H
#define NCTA_REC 128

typedef unsigned long long ull;

// ---------------- scratch (module-load allocated) ----------------
__device__ float g_xg [(size_t)Sdim * Bdim * Gdim];               // [s*B+b][4H]
__device__ __align__(16) __nv_bfloat16 g_Ahi [(size_t)Sdim * Bdim * Hdim];
__device__ __align__(16) __nv_bfloat16 g_Alo [(size_t)Sdim * Bdim * Hdim];
__device__ __align__(16) __nv_bfloat16 g_h1hi[(size_t)Sdim * Bdim * Hdim];
__device__ __align__(16) __nv_bfloat16 g_h1lo[(size_t)Sdim * Bdim * Hdim];
__device__ __align__(16) __nv_bfloat16 g_Whi [2 * (size_t)Gdim * Hdim];
__device__ __align__(16) __nv_bfloat16 g_Wlo [2 * (size_t)Gdim * Hdim];
__device__ __align__(16) __nv_bfloat16 g_hb_hi[2][Bdim * Hdim];   // ping-pong h split
__device__ __align__(16) __nv_bfloat16 g_hb_lo[2][Bdim * Hdim];
__device__ unsigned g_cnt;    // init barrier
__device__ unsigned g_gen;    // init barrier
__device__ unsigned g_cnt2;   // per-step monotonic arrival counter

// ---------------- PTX helpers ----------------
__device__ __forceinline__ uint32_t smem_u32(const void* p) {
    uint32_t a;
    asm("{ .reg .u64 t; cvta.to.shared.u64 t, %1; cvt.u32.u64 %0, t; }" : "=r"(a) : "l"(p));
    return a;
}
#define CP_ASYNC16(dst, src) \
    asm volatile("cp.async.cg.shared.global [%0], [%1], 16;" :: "r"(dst), "l"(src))
#define CP_COMMIT() asm volatile("cp.async.commit_group;" ::: "memory")
#define CP_WAIT1()  asm volatile("cp.async.wait_group 1;" ::: "memory")
#define CP_WAIT0()  asm volatile("cp.async.wait_group 0;" ::: "memory")

__device__ __forceinline__ void ldm_x4(uint32_t* r, uint32_t addr) {
    asm volatile("ldmatrix.sync.aligned.m8n8.x4.shared.b16 {%0,%1,%2,%3}, [%4];"
                 : "=r"(r[0]), "=r"(r[1]), "=r"(r[2]), "=r"(r[3]) : "r"(addr));
}
__device__ __forceinline__ void mma_bf16(float* d, const uint32_t* a, const uint32_t* b) {
    asm volatile(
        "mma.sync.aligned.m16n8k16.row.col.f32.bf16.bf16.f32 "
        "{%0,%1,%2,%3}, {%4,%5,%6,%7}, {%8,%9}, {%0,%1,%2,%3};"
        : "+f"(d[0]), "+f"(d[1]), "+f"(d[2]), "+f"(d[3])
        : "r"(a[0]), "r"(a[1]), "r"(a[2]), "r"(a[3]), "r"(b[0]), "r"(b[1]));
}

// ---------------- init grid barrier (validated R1/R4/R6; replay-safe) ----------------
__device__ __forceinline__ void grid_barrier() {
    __syncthreads();
    if (threadIdx.x == 0) {
        __threadfence();
        unsigned gen = *(volatile unsigned*)&g_gen;
        unsigned old = atomicAdd(&g_cnt, 1u);
        if (old == gridDim.x - 1) {
            atomicExch(&g_cnt, 0u);
            __threadfence();
            atomicAdd(&g_gen, 1u);
        } else {
            while (*(volatile unsigned*)&g_gen == gen) { __nanosleep(32); }
        }
        __threadfence();
    }
    __syncthreads();
}

// ---------------- fp32 -> bf16 hi/lo split ----------------
__device__ __forceinline__ void split4(float4 v, ull& hi, ull& lo) {
    union { __nv_bfloat16 h[4]; ull u; } H, L;
    float f[4] = {v.x, v.y, v.z, v.w};
#pragma unroll
    for (int i = 0; i < 4; i++) {
        __nv_bfloat16 a = __float2bfloat16_rn(f[i]);
        H.h[i] = a;
        L.h[i] = __float2bfloat16_rn(f[i] - __bfloat162float(a));
    }
    hi = H.u; lo = L.u;
}

// X[b][s][k] -> g_Ahi/g_Alo[(s*B+b)][k]
__global__ __launch_bounds__(256) void conv_x_kernel(const float* __restrict__ X) {
    size_t i = (size_t)blockIdx.x * 256 + threadIdx.x;
    int row = (int)(i >> 7);
    int c4  = (int)(i & 127);
    int b = row & 31, s = row >> 5;
    float4 v = __ldg((const float4*)(X + ((size_t)b * Sdim + s) * Hdim + c4 * 4));
    ull hi, lo;
    split4(v, hi, lo);
    *(ull*)(g_Ahi + (size_t)row * Hdim + c4 * 4) = hi;
    *(ull*)(g_Alo + (size_t)row * Hdim + c4 * 4) = lo;
}

// Wih[2][4H][H] -> g_Whi/g_Wlo
__global__ __launch_bounds__(256) void conv_w_kernel(const float* __restrict__ W) {
    size_t i = (size_t)blockIdx.x * 256 + threadIdx.x;
    float4 v = __ldg((const float4*)W + i);
    ull hi, lo;
    split4(v, hi, lo);
    *(ull*)(g_Whi + i * 4) = hi;
    *(ull*)(g_Wlo + i * 4) = lo;
}

// ---------------- mma.sync split-bf16 GEMM (validated R4) ----------------
#define TSTRIDE 80
#define MAT_B   (128 * TSTRIDE)
#define STAGE_B (4 * MAT_B)

__global__ __launch_bounds__(256, 1) void gemm_mma_kernel(
    int src_h1, int layer,
    const float* __restrict__ bih, const float* __restrict__ bhh)
{
    extern __shared__ char smem[];
    uint32_t sb = smem_u32(smem);
    int tid = threadIdx.x, wid = tid >> 5, lane = tid & 31;
    int col0 = blockIdx.x * 128;
    int row0 = blockIdx.y * 128;
    int wm = wid & 1, wn = wid >> 1;

    const __nv_bfloat16* a0p = (src_h1 ? g_h1hi : g_Ahi) + (size_t)row0 * Hdim;
    const __nv_bfloat16* a1p = (src_h1 ? g_h1lo : g_Alo) + (size_t)row0 * Hdim;
    const __nv_bfloat16* w0p = g_Whi + (size_t)layer * Gdim * Hdim + (size_t)col0 * Hdim;
    const __nv_bfloat16* w1p = g_Wlo + (size_t)layer * Gdim * Hdim + (size_t)col0 * Hdim;

    int ldr  = tid >> 2;
    int ldkc = tid & 3;

#define PREFETCH(stg, k0)                                                         \
    do {                                                                          \
        _Pragma("unroll")                                                         \
        for (int m = 0; m < 4; m++) {                                             \
            const __nv_bfloat16* mp = (m == 0 ? a0p : m == 1 ? a1p :              \
                                       m == 2 ? w0p : w1p);                       \
            _Pragma("unroll")                                                     \
            for (int i = 0; i < 2; i++) {                                         \
                int r = ldr + i * 64;                                             \
                uint32_t dst = sb + (stg) * STAGE_B + m * MAT_B +                 \
                               r * TSTRIDE + ldkc * 16;                           \
                const void* srcp = mp + (size_t)r * Hdim + (k0) + ldkc * 8;       \
                CP_ASYNC16(dst, srcp);                                            \
            }                                                                     \
        }                                                                         \
        CP_COMMIT();                                                              \
    } while (0)

    float acc[4][4][4];
#pragma unroll
    for (int i = 0; i < 4; i++)
#pragma unroll
        for (int j = 0; j < 4; j++)
#pragma unroll
            for (int k = 0; k < 4; k++) acc[i][j][k] = 0.0f;

    PREFETCH(0, 0);
    PREFETCH(1, 32);

    int tile = lane >> 3, trow = lane & 7;

    for (int kt = 0; kt < 16; kt++) {
        if (kt == 15) CP_WAIT0(); else CP_WAIT1();
        __syncthreads();
        uint32_t base = sb + (kt & 1) * STAGE_B;

#pragma unroll
        for (int ks = 0; ks < 2; ks++) {
            uint32_t ahi[4][4], alo[4][4];
#pragma unroll
            for (int mf = 0; mf < 4; mf++) {
                int row = wm * 64 + mf * 16 + (tile & 1) * 8 + trow;
                int col = ks * 16 + (tile >> 1) * 8;
                ldm_x4(ahi[mf], base + 0 * MAT_B + row * TSTRIDE + col * 2);
                ldm_x4(alo[mf], base + 1 * MAT_B + row * TSTRIDE + col * 2);
            }
            uint32_t bhi[4][2], blo[4][2];
#pragma unroll
            for (int p = 0; p < 2; p++) {
                int rn = wn * 32 + p * 16 + (tile >> 1) * 8 + trow;
                int ck = ks * 16 + (tile & 1) * 8;
                uint32_t r4[4];
                ldm_x4(r4, base + 2 * MAT_B + rn * TSTRIDE + ck * 2);
                bhi[2*p][0] = r4[0]; bhi[2*p][1] = r4[1];
                bhi[2*p+1][0] = r4[2]; bhi[2*p+1][1] = r4[3];
                ldm_x4(r4, base + 3 * MAT_B + rn * TSTRIDE + ck * 2);
                blo[2*p][0] = r4[0]; blo[2*p][1] = r4[1];
                blo[2*p+1][0] = r4[2]; blo[2*p+1][1] = r4[3];
            }
#pragma unroll
            for (int mf = 0; mf < 4; mf++)
#pragma unroll
                for (int nf = 0; nf < 4; nf++) {
                    mma_bf16(acc[mf][nf], ahi[mf], bhi[nf]);
                    mma_bf16(acc[mf][nf], ahi[mf], blo[nf]);
                    mma_bf16(acc[mf][nf], alo[mf], bhi[nf]);
                }
        }
        __syncthreads();
        if (kt < 14) PREFETCH(kt & 1, (kt + 2) * 32);
    }

#pragma unroll
    for (int mf = 0; mf < 4; mf++) {
        int r0 = row0 + wm * 64 + mf * 16 + (lane >> 2);
#pragma unroll
        for (int nf = 0; nf < 4; nf++) {
            int cb = col0 + wn * 32 + nf * 8 + 2 * (lane & 3);
            float b0v = __ldg(&bih[cb])     + __ldg(&bhh[cb]);
            float b1v = __ldg(&bih[cb + 1]) + __ldg(&bhh[cb + 1]);
            *(float2*)&g_xg[(size_t)r0 * Gdim + cb] =
                make_float2(acc[mf][nf][0] + b0v, acc[mf][nf][1] + b1v);
            *(float2*)&g_xg[(size_t)(r0 + 8) * Gdim + cb] =
                make_float2(acc[mf][nf][2] + b0v, acc[mf][nf][3] + b1v);
        }
    }
#undef PREFETCH
}

// ---------------- persistent recurrence on tensor cores ----------------
// 128 CTAs x 256 threads (R6 layout). CTA owns 4 hidden units (16 gate cols).
// Split-phase monotonic-counter barrier; non-critical writes in overlap window.
#define RSTRIDE 1040   // bytes per smem bf16 row of 512 (+8 pad elems)
#define RED_OFF (96 * RSTRIDE)

__global__ __launch_bounds__(256, 1) void lstm_recur_mma(
    const float* __restrict__ Whh, float* __restrict__ hseq,
    int out_bsh, float* __restrict__ hTo, float* __restrict__ cTo)
{
    extern __shared__ char sm[];
    uint32_t sb = smem_u32(sm);
    uint32_t sWhi = sb;
    uint32_t sWlo = sb + 16 * RSTRIDE;
    uint32_t sHhi = sb + 32 * RSTRIDE;
    uint32_t sHlo = sb + 64 * RSTRIDE;
    float* red = (float*)(sm + RED_OFF);   // [8][32][18]

    int tid = threadIdx.x, wid = tid >> 5, lane = tid & 31;
    int b  = tid & 31;
    int jj = (tid >> 5) & 3;
    int j0 = blockIdx.x * 4;

    // stage Whh (split bf16) to smem: row r = q*4 + j  <-  Whh[q*512 + j0 + j]
    for (int idx = tid; idx < 2048; idx += 256) {
        int r = idx >> 7, c4 = idx & 127;
        int q = r >> 2, j = r & 3;
        float4 v = __ldg((const float4*)(Whh + (size_t)(q * Hdim + j0 + j) * Hdim + c4 * 4));
        ull hi, lo;
        split4(v, hi, lo);
        *(ull*)(sm + r * RSTRIDE + c4 * 8) = hi;
        *(ull*)(sm + 16 * RSTRIDE + r * RSTRIDE + c4 * 8) = lo;
    }
    if (blockIdx.x == 0 && tid == 0) g_cnt2 = 0u;   // reset step counter (per launch)
    if (tid < 128) {
        g_hb_hi[0][b * Hdim + j0 + jj] = __float2bfloat16(0.0f);
        g_hb_lo[0][b * Hdim + j0 + jj] = __float2bfloat16(0.0f);
    }
    __syncthreads();

    // preload B fragments: warp w owns k in [w*64, w*64+64)
    int kbase = wid * 64;
    int tile = lane >> 3, trow = lane & 7;
    uint32_t bhi[4][2][2], blo[4][2][2];
#pragma unroll
    for (int kt = 0; kt < 4; kt++) {
        int row = (tile >> 1) * 8 + trow;
        int col = kbase + kt * 16 + (tile & 1) * 8;
        uint32_t r4[4];
        ldm_x4(r4, sWhi + row * RSTRIDE + col * 2);
        bhi[kt][0][0] = r4[0]; bhi[kt][0][1] = r4[1];
        bhi[kt][1][0] = r4[2]; bhi[kt][1][1] = r4[3];
        ldm_x4(r4, sWlo + row * RSTRIDE + col * 2);
        blo[kt][0][0] = r4[0]; blo[kt][0][1] = r4[1];
        blo[kt][1][0] = r4[2]; blo[kt][1][1] = r4[3];
    }
    grid_barrier();   // h(0), g_cnt2 reset visible everywhere

    float c_st = 0.0f;
    const float* xg_base = g_xg + (size_t)b * Gdim + (j0 + jj);
    // xg for step 0
    float x_i = __ldg(xg_base + 0 * Hdim);
    float x_f = __ldg(xg_base + 1 * Hdim);
    float x_g = __ldg(xg_base + 2 * Hdim);
    float x_o = __ldg(xg_base + 3 * Hdim);

    for (int t = 0; t < Sdim; t++) {
        int cur = t & 1;

        // WAIT phase: all CTAs arrived t times (step t-1 complete). t=0 covered by init barrier.
        if (t > 0) {
            if (tid == 0) {
                unsigned target = (unsigned)t * NCTA_REC;
                while (*(volatile unsigned*)&g_cnt2 < target) { }
                __threadfence();
            }
            __syncthreads();
        }

        // stage h(t-1) split: 2 x 32KB -> smem
        const char* srchi = (const char*)g_hb_hi[cur];
        const char* srclo = (const char*)g_hb_lo[cur];
#pragma unroll
        for (int i = 0; i < 8; i++) {
            int idx = tid + i * 256;          // 0..2047 (16B chunks)
            int r = idx >> 6, ch = idx & 63;
            CP_ASYNC16(sHhi + r * RSTRIDE + ch * 16, srchi + idx * 16);
            CP_ASYNC16(sHlo + r * RSTRIDE + ch * 16, srclo + idx * 16);
        }
        CP_COMMIT();
        CP_WAIT0();
        __syncthreads();

        // MMA: [32 x 64-slice] x [64-slice x 16] partials
        float acc[2][2][4];
#pragma unroll
        for (int i = 0; i < 2; i++)
#pragma unroll
            for (int j = 0; j < 2; j++)
#pragma unroll
                for (int k = 0; k < 4; k++) acc[i][j][k] = 0.0f;

#pragma unroll
        for (int kt = 0; kt < 4; kt++) {
            int colb = kbase + kt * 16 + (tile >> 1) * 8;
            uint32_t ahi[2][4], alo[2][4];
#pragma unroll
            for (int mf = 0; mf < 2; mf++) {
                int row = mf * 16 + (tile & 1) * 8 + trow;
                ldm_x4(ahi[mf], sHhi + row * RSTRIDE + colb * 2);
                ldm_x4(alo[mf], sHlo + row * RSTRIDE + colb * 2);
            }
#pragma unroll
            for (int mf = 0; mf < 2; mf++)
#pragma unroll
                for (int nf = 0; nf < 2; nf++) {
                    mma_bf16(acc[mf][nf], ahi[mf], bhi[kt][nf]);
                    mma_bf16(acc[mf][nf], ahi[mf], blo[kt][nf]);
                    mma_bf16(acc[mf][nf], alo[mf], bhi[kt][nf]);
                }
        }

        // per-warp partials -> red[wid][m 0..31][n 0..15]
#pragma unroll
        for (int mf = 0; mf < 2; mf++)
#pragma unroll
            for (int nf = 0; nf < 2; nf++) {
                int row = mf * 16 + (lane >> 2);
                int col = nf * 8 + (lane & 3) * 2;
                float* p0 = red + ((wid * 32 + row) * 18 + col);
                p0[0] = acc[mf][nf][0]; p0[1] = acc[mf][nf][1];
                float* p1 = red + ((wid * 32 + row + 8) * 18 + col);
                p1[0] = acc[mf][nf][2]; p1[1] = acc[mf][nf][3];
            }
        __syncthreads();

        float h = 0.0f;
        __nv_bfloat16 hh, hl;
        if (tid < 128) {
            float di = x_i, df = x_f, dg = x_g, do_ = x_o;
#pragma unroll
            for (int w = 0; w < 8; w++) {
                const float* rr = red + (w * 32 + b) * 18;
                di  += rr[0 * 4 + jj];
                df  += rr[1 * 4 + jj];
                dg  += rr[2 * 4 + jj];
                do_ += rr[3 * 4 + jj];
            }
            float ig = 1.0f / (1.0f + __expf(-di));
            float fg = 1.0f / (1.0f + __expf(-df));
            float gg = tanhf(dg);
            float og = 1.0f / (1.0f + __expf(-do_));
            c_st = fg * c_st + ig * gg;
            h = og * tanhf(c_st);

            hh = __float2bfloat16_rn(h);
            hl = __float2bfloat16_rn(h - __bfloat162float(hh));
            // CRITICAL write: next step's input
            g_hb_hi[cur ^ 1][b * Hdim + j0 + jj] = hh;
            g_hb_lo[cur ^ 1][b * Hdim + j0 + jj] = hl;
            __threadfence();   // release h(t) before arrive
        }
        __syncthreads();

        // ARRIVE (atomic RMW release, same strong-op pattern as validated barrier)
        if (tid == 0) atomicAdd(&g_cnt2, 1u);

        // ---- overlap window: non-critical writes + next-step xg prefetch ----
        if (tid < 128) {
            if (out_bsh) {
                hseq[((size_t)b * Sdim + t) * Hdim + j0 + jj] = h;
                if (hTo && t == Sdim - 1) {
                    hTo[b * Hdim + j0 + jj] = h;
                    cTo[b * Hdim + j0 + jj] = c_st;
                }
            } else {
                size_t r = ((size_t)t * Bdim + b) * Hdim + j0 + jj;
                g_h1hi[r] = hh;
                g_h1lo[r] = hl;
            }
        }
        if (t + 1 < Sdim) {
            xg_base += (size_t)Bdim * Gdim;
            x_i = __ldg(xg_base + 0 * Hdim);
            x_f = __ldg(xg_base + 1 * Hdim);
            x_g = __ldg(xg_base + 2 * Hdim);
            x_o = __ldg(xg_base + 3 * Hdim);
        }
    }
}

// ---------------- launch ----------------
extern "C" void kernel_launch(void* const* d_in, const int* in_sizes, int n_in,
                              void* d_out, int out_size) {
    (void)in_sizes; (void)n_in;
    const float* X   = (const float*)d_in[0];
    const float* Wih = (const float*)d_in[1];
    const float* Whh = (const float*)d_in[2];
    const float* bih = (const float*)d_in[3];
    const float* bhh = (const float*)d_in[4];
    float* out = (float*)d_out;

    size_t ht_elems = (size_t)Bdim * Sdim * Hdim;
    float* hTo = nullptr; float* cTo = nullptr;
    if ((size_t)out_size >= ht_elems + 2 * (size_t)Bdim * Hdim) {
        hTo = out + ht_elems;
        cTo = hTo + (size_t)Bdim * Hdim;
    }

    const int smem_rec  = RED_OFF + 8 * 32 * 18 * 4;    // 118272
    const int smem_gemm = 2 * STAGE_B;                  // 81920
    cudaFuncSetAttribute(lstm_recur_mma,
                         cudaFuncAttributeMaxDynamicSharedMemorySize, smem_rec);
    cudaFuncSetAttribute(gemm_mma_kernel,
                         cudaFuncAttributeMaxDynamicSharedMemorySize, smem_gemm);

    conv_w_kernel<<<2048, 256>>>(Wih);
    conv_x_kernel<<<32768, 256>>>(X);

    dim3 ggrid(Gdim / 128, (Sdim * Bdim) / 128);   // (16, 512)

    // Layer 0
    gemm_mma_kernel<<<ggrid, 256, smem_gemm>>>(0, 0, bih, bhh);
    lstm_recur_mma<<<NCTA_REC, 256, smem_rec>>>(Whh, nullptr, 0, nullptr, nullptr);
    // Layer 1
    gemm_mma_kernel<<<ggrid, 256, smem_gemm>>>(1, 1, bih + Gdim, bhh + Gdim);
    lstm_recur_mma<<<NCTA_REC, 256, smem_rec>>>(Whh + (size_t)Gdim * Hdim,
                                                out, 1, hTo, cTo);
}

// round 14
// speedup vs baseline: 1.6224x; 1.3070x over previous
#include <cuda_runtime.h>
#include <cuda_bf16.h>
#include <cstdint>

#define Sdim 2048
#define Bdim 32
#define Hdim 512
#define Gdim 2048   // 4*H
#define NCTA_REC 128

typedef unsigned long long ull;

// ---------------- scratch (module-load allocated) ----------------
__device__ float g_xg [(size_t)Sdim * Bdim * Gdim];               // layer-1 gates [s*B+b][4H]
__device__ __align__(16) __nv_bfloat16 g_Ahi [(size_t)Sdim * Bdim * Hdim];
__device__ __align__(16) __nv_bfloat16 g_Alo [(size_t)Sdim * Bdim * Hdim];
__device__ __align__(16) __nv_bfloat16 g_Whi [(size_t)Gdim * Hdim];   // layer-0 Wih split
__device__ __align__(16) __nv_bfloat16 g_Wlo [(size_t)Gdim * Hdim];
__device__ __align__(16) __nv_bfloat16 g_h1b_hi[2][Bdim * Hdim];  // ping-pong h1 split
__device__ __align__(16) __nv_bfloat16 g_h1b_lo[2][Bdim * Hdim];
__device__ __align__(16) __nv_bfloat16 g_h2b_hi[2][Bdim * Hdim];  // ping-pong h2 split
__device__ __align__(16) __nv_bfloat16 g_h2b_lo[2][Bdim * Hdim];
__device__ unsigned g_cnt;    // init barrier
__device__ unsigned g_gen;    // init barrier
__device__ unsigned g_cnt2;   // per-step monotonic arrival counter

// ---------------- PTX helpers ----------------
__device__ __forceinline__ uint32_t smem_u32(const void* p) {
    uint32_t a;
    asm("{ .reg .u64 t; cvta.to.shared.u64 t, %1; cvt.u32.u64 %0, t; }" : "=r"(a) : "l"(p));
    return a;
}
#define CP_ASYNC16(dst, src) \
    asm volatile("cp.async.cg.shared.global [%0], [%1], 16;" :: "r"(dst), "l"(src))
#define CP_COMMIT() asm volatile("cp.async.commit_group;" ::: "memory")
#define CP_WAIT1()  asm volatile("cp.async.wait_group 1;" ::: "memory")
#define CP_WAIT0()  asm volatile("cp.async.wait_group 0;" ::: "memory")

__device__ __forceinline__ void ldm_x4(uint32_t* r, uint32_t addr) {
    asm volatile("ldmatrix.sync.aligned.m8n8.x4.shared.b16 {%0,%1,%2,%3}, [%4];"
                 : "=r"(r[0]), "=r"(r[1]), "=r"(r[2]), "=r"(r[3]) : "r"(addr));
}
__device__ __forceinline__ void mma_bf16(float* d, const uint32_t* a, const uint32_t* b) {
    asm volatile(
        "mma.sync.aligned.m16n8k16.row.col.f32.bf16.bf16.f32 "
        "{%0,%1,%2,%3}, {%4,%5,%6,%7}, {%8,%9}, {%0,%1,%2,%3};"
        : "+f"(d[0]), "+f"(d[1]), "+f"(d[2]), "+f"(d[3])
        : "r"(a[0]), "r"(a[1]), "r"(a[2]), "r"(a[3]), "r"(b[0]), "r"(b[1]));
}

// ---------------- init grid barrier (validated; replay-safe) ----------------
__device__ __forceinline__ void grid_barrier() {
    __syncthreads();
    if (threadIdx.x == 0) {
        __threadfence();
        unsigned gen = *(volatile unsigned*)&g_gen;
        unsigned old = atomicAdd(&g_cnt, 1u);
        if (old == gridDim.x - 1) {
            atomicExch(&g_cnt, 0u);
            __threadfence();
            atomicAdd(&g_gen, 1u);
        } else {
            while (*(volatile unsigned*)&g_gen == gen) { __nanosleep(32); }
        }
        __threadfence();
    }
    __syncthreads();
}

// ---------------- fp32 -> bf16 hi/lo split ----------------
__device__ __forceinline__ void split4(float4 v, ull& hi, ull& lo) {
    union { __nv_bfloat16 h[4]; ull u; } H, L;
    float f[4] = {v.x, v.y, v.z, v.w};
#pragma unroll
    for (int i = 0; i < 4; i++) {
        __nv_bfloat16 a = __float2bfloat16_rn(f[i]);
        H.h[i] = a;
        L.h[i] = __float2bfloat16_rn(f[i] - __bfloat162float(a));
    }
    hi = H.u; lo = L.u;
}

// X[b][s][k] -> g_Ahi/g_Alo[(s*B+b)][k]
__global__ __launch_bounds__(256) void conv_x_kernel(const float* __restrict__ X) {
    size_t i = (size_t)blockIdx.x * 256 + threadIdx.x;
    int row = (int)(i >> 7);
    int c4  = (int)(i & 127);
    int b = row & 31, s = row >> 5;
    float4 v = __ldg((const float4*)(X + ((size_t)b * Sdim + s) * Hdim + c4 * 4));
    ull hi, lo;
    split4(v, hi, lo);
    *(ull*)(g_Ahi + (size_t)row * Hdim + c4 * 4) = hi;
    *(ull*)(g_Alo + (size_t)row * Hdim + c4 * 4) = lo;
}

// Wih[0][4H][H] -> g_Whi/g_Wlo (layer 0 only)
__global__ __launch_bounds__(256) void conv_w_kernel(const float* __restrict__ W) {
    size_t i = (size_t)blockIdx.x * 256 + threadIdx.x;   // 262144 float4's
    float4 v = __ldg((const float4*)W + i);
    ull hi, lo;
    split4(v, hi, lo);
    *(ull*)(g_Whi + i * 4) = hi;
    *(ull*)(g_Wlo + i * 4) = lo;
}

// ---------------- mma.sync split-bf16 GEMM (validated R4; layer-0 xg only) ----------------
#define TSTRIDE 80
#define MAT_B   (128 * TSTRIDE)
#define STAGE_B (4 * MAT_B)

__global__ __launch_bounds__(256, 1) void gemm_mma_kernel(
    const float* __restrict__ bih, const float* __restrict__ bhh)
{
    extern __shared__ char smem[];
    uint32_t sb = smem_u32(smem);
    int tid = threadIdx.x, wid = tid >> 5, lane = tid & 31;
    int col0 = blockIdx.x * 128;
    int row0 = blockIdx.y * 128;
    int wm = wid & 1, wn = wid >> 1;

    const __nv_bfloat16* a0p = g_Ahi + (size_t)row0 * Hdim;
    const __nv_bfloat16* a1p = g_Alo + (size_t)row0 * Hdim;
    const __nv_bfloat16* w0p = g_Whi + (size_t)col0 * Hdim;
    const __nv_bfloat16* w1p = g_Wlo + (size_t)col0 * Hdim;

    int ldr  = tid >> 2;
    int ldkc = tid & 3;

#define PREFETCH(stg, k0)                                                         \
    do {                                                                          \
        _Pragma("unroll")                                                         \
        for (int m = 0; m < 4; m++) {                                             \
            const __nv_bfloat16* mp = (m == 0 ? a0p : m == 1 ? a1p :              \
                                       m == 2 ? w0p : w1p);                       \
            _Pragma("unroll")                                                     \
            for (int i = 0; i < 2; i++) {                                         \
                int r = ldr + i * 64;                                             \
                uint32_t dst = sb + (stg) * STAGE_B + m * MAT_B +                 \
                               r * TSTRIDE + ldkc * 16;                           \
                const void* srcp = mp + (size_t)r * Hdim + (k0) + ldkc * 8;       \
                CP_ASYNC16(dst, srcp);                                            \
            }                                                                     \
        }                                                                         \
        CP_COMMIT();                                                              \
    } while (0)

    float acc[4][4][4];
#pragma unroll
    for (int i = 0; i < 4; i++)
#pragma unroll
        for (int j = 0; j < 4; j++)
#pragma unroll
            for (int k = 0; k < 4; k++) acc[i][j][k] = 0.0f;

    PREFETCH(0, 0);
    PREFETCH(1, 32);

    int tile = lane >> 3, trow = lane & 7;

    for (int kt = 0; kt < 16; kt++) {
        if (kt == 15) CP_WAIT0(); else CP_WAIT1();
        __syncthreads();
        uint32_t base = sb + (kt & 1) * STAGE_B;

#pragma unroll
        for (int ks = 0; ks < 2; ks++) {
            uint32_t ahi[4][4], alo[4][4];
#pragma unroll
            for (int mf = 0; mf < 4; mf++) {
                int row = wm * 64 + mf * 16 + (tile & 1) * 8 + trow;
                int col = ks * 16 + (tile >> 1) * 8;
                ldm_x4(ahi[mf], base + 0 * MAT_B + row * TSTRIDE + col * 2);
                ldm_x4(alo[mf], base + 1 * MAT_B + row * TSTRIDE + col * 2);
            }
            uint32_t bhi[4][2], blo[4][2];
#pragma unroll
            for (int p = 0; p < 2; p++) {
                int rn = wn * 32 + p * 16 + (tile >> 1) * 8 + trow;
                int ck = ks * 16 + (tile & 1) * 8;
                uint32_t r4[4];
                ldm_x4(r4, base + 2 * MAT_B + rn * TSTRIDE + ck * 2);
                bhi[2*p][0] = r4[0]; bhi[2*p][1] = r4[1];
                bhi[2*p+1][0] = r4[2]; bhi[2*p+1][1] = r4[3];
                ldm_x4(r4, base + 3 * MAT_B + rn * TSTRIDE + ck * 2);
                blo[2*p][0] = r4[0]; blo[2*p][1] = r4[1];
                blo[2*p+1][0] = r4[2]; blo[2*p+1][1] = r4[3];
            }
#pragma unroll
            for (int mf = 0; mf < 4; mf++)
#pragma unroll
                for (int nf = 0; nf < 4; nf++) {
                    mma_bf16(acc[mf][nf], ahi[mf], bhi[nf]);
                    mma_bf16(acc[mf][nf], ahi[mf], blo[nf]);
                    mma_bf16(acc[mf][nf], alo[mf], bhi[nf]);
                }
        }
        __syncthreads();
        if (kt < 14) PREFETCH(kt & 1, (kt + 2) * 32);
    }

#pragma unroll
    for (int mf = 0; mf < 4; mf++) {
        int r0 = row0 + wm * 64 + mf * 16 + (lane >> 2);
#pragma unroll
        for (int nf = 0; nf < 4; nf++) {
            int cb = col0 + wn * 32 + nf * 8 + 2 * (lane & 3);
            float b0v = __ldg(&bih[cb])     + __ldg(&bhh[cb]);
            float b1v = __ldg(&bih[cb + 1]) + __ldg(&bhh[cb + 1]);
            *(float2*)&g_xg[(size_t)r0 * Gdim + cb] =
                make_float2(acc[mf][nf][0] + b0v, acc[mf][nf][1] + b1v);
            *(float2*)&g_xg[(size_t)(r0 + 8) * Gdim + cb] =
                make_float2(acc[mf][nf][2] + b0v, acc[mf][nf][3] + b1v);
        }
    }
#undef PREFETCH
}

// ---------------- fused 2-layer wavefront recurrence ----------------
// 128 CTAs x 256 threads. CTA owns hidden units j0..j0+3 of BOTH layers.
// Step t: layer1 computes h1(t) (t<2048); layer2 computes h2(t-1) (t>=1).
// 3 register-resident W-frag sets (Whh1, Wih2, Whh2), all split bf16.
#define RSTRIDE 1040                     // bytes per smem bf16 row of 512 (+pad)
#define RED1_OFF (128 * RSTRIDE)         // 133120
#define RED2_OFF (RED1_OFF + 8*32*18*4)  // +18432

__global__ __launch_bounds__(256, 1) void lstm_fused(
    const float* __restrict__ Whh1, const float* __restrict__ Wih2,
    const float* __restrict__ Whh2,
    const float* __restrict__ bih2, const float* __restrict__ bhh2,
    float* __restrict__ hseq, float* __restrict__ hTo, float* __restrict__ cTo)
{
    extern __shared__ char sm[];
    uint32_t sb = smem_u32(sm);
    uint32_t sH1hi = sb;
    uint32_t sH1lo = sb + 32 * RSTRIDE;
    uint32_t sH2hi = sb + 64 * RSTRIDE;
    uint32_t sH2lo = sb + 96 * RSTRIDE;
    float* red1 = (float*)(sm + RED1_OFF);   // [8][32][18]
    float* red2 = (float*)(sm + RED2_OFF);   // [8][32][18]

    int tid = threadIdx.x, wid = tid >> 5, lane = tid & 31;
    int b  = tid & 31;
    int jj = (tid >> 5) & 3;
    int j0 = blockIdx.x * 4;

    int kbase = wid * 64;
    int tile = lane >> 3, trow = lane & 7;

    // ---- init: load 3 W-frag sets via smem staging (reuse sH1 areas) ----
    uint32_t w1h[4][2][2],  w1l[4][2][2];
    uint32_t w2ih[4][2][2], w2il[4][2][2];
    uint32_t w2hh[4][2][2], w2hl[4][2][2];

#define LOAD_WFRAGS(Wsrc, Fh, Fl)                                                  \
    do {                                                                           \
        for (int idx = tid; idx < 2048; idx += 256) {                              \
            int r = idx >> 7, c4 = idx & 127;                                      \
            int q = r >> 2, j = r & 3;                                             \
            float4 v = __ldg((const float4*)((Wsrc) +                              \
                        (size_t)(q * Hdim + j0 + j) * Hdim + c4 * 4));             \
            ull hi, lo;                                                            \
            split4(v, hi, lo);                                                     \
            *(ull*)(sm + r * RSTRIDE + c4 * 8) = hi;                               \
            *(ull*)(sm + 32 * RSTRIDE + r * RSTRIDE + c4 * 8) = lo;                \
        }                                                                          \
        __syncthreads();                                                           \
        _Pragma("unroll")                                                          \
        for (int kt = 0; kt < 4; kt++) {                                           \
            int row = (tile >> 1) * 8 + trow;                                      \
            int col = kbase + kt * 16 + (tile & 1) * 8;                            \
            uint32_t r4[4];                                                        \
            ldm_x4(r4, sH1hi + row * RSTRIDE + col * 2);                           \
            Fh[kt][0][0] = r4[0]; Fh[kt][0][1] = r4[1];                            \
            Fh[kt][1][0] = r4[2]; Fh[kt][1][1] = r4[3];                            \
            ldm_x4(r4, sH1lo + row * RSTRIDE + col * 2);                           \
            Fl[kt][0][0] = r4[0]; Fl[kt][0][1] = r4[1];                            \
            Fl[kt][1][0] = r4[2]; Fl[kt][1][1] = r4[3];                            \
        }                                                                          \
        __syncthreads();                                                           \
    } while (0)

    LOAD_WFRAGS(Whh1, w1h,  w1l);
    LOAD_WFRAGS(Wih2, w2ih, w2il);
    LOAD_WFRAGS(Whh2, w2hh, w2hl);
#undef LOAD_WFRAGS

    // layer-2 per-thread bias (gate cols q*512 + j0+jj)
    float bias2[4];
#pragma unroll
    for (int q = 0; q < 4; q++)
        bias2[q] = __ldg(&bih2[q * Hdim + j0 + jj]) + __ldg(&bhh2[q * Hdim + j0 + jj]);

    if (blockIdx.x == 0 && tid == 0) g_cnt2 = 0u;
    if (tid < 128) {   // h1(-1)=0 in buf[0]; h2(-1)=0 in buf[1]
        g_h1b_hi[0][b * Hdim + j0 + jj] = __float2bfloat16(0.0f);
        g_h1b_lo[0][b * Hdim + j0 + jj] = __float2bfloat16(0.0f);
        g_h2b_hi[1][b * Hdim + j0 + jj] = __float2bfloat16(0.0f);
        g_h2b_lo[1][b * Hdim + j0 + jj] = __float2bfloat16(0.0f);
    }
    grid_barrier();   // zeros + counter reset visible everywhere

    float c1 = 0.0f, c2 = 0.0f;
    const float* xg_base = g_xg + (size_t)b * Gdim + (j0 + jj);
    float x_i = __ldg(xg_base + 0 * Hdim);
    float x_f = __ldg(xg_base + 1 * Hdim);
    float x_g = __ldg(xg_base + 2 * Hdim);
    float x_o = __ldg(xg_base + 3 * Hdim);

    for (int t = 0; t <= Sdim; t++) {
        int cur = t & 1;

        // WAIT: all CTAs completed step t-1
        if (t > 0) {
            if (tid == 0) {
                unsigned target = (unsigned)t * NCTA_REC;
                while (*(volatile unsigned*)&g_cnt2 < target) { }
                __threadfence();
            }
            __syncthreads();
        }

        // stage h1(t-1) + h2(t-2), split: 4 x 32KB -> smem
        {
            const char* s0 = (const char*)g_h1b_hi[cur];
            const char* s1 = (const char*)g_h1b_lo[cur];
            const char* s2 = (const char*)g_h2b_hi[cur];
            const char* s3 = (const char*)g_h2b_lo[cur];
#pragma unroll
            for (int i = 0; i < 8; i++) {
                int idx = tid + i * 256;          // 0..2047
                int r = idx >> 6, ch = idx & 63;
                uint32_t off = r * RSTRIDE + ch * 16;
                CP_ASYNC16(sH1hi + off, s0 + idx * 16);
                CP_ASYNC16(sH1lo + off, s1 + idx * 16);
                CP_ASYNC16(sH2hi + off, s2 + idx * 16);
                CP_ASYNC16(sH2lo + off, s3 + idx * 16);
            }
        }
        CP_COMMIT();
        CP_WAIT0();
        __syncthreads();

        // MMA: acc1 = Whh1 @ h1(t-1); acc2 = Wih2 @ h1(t-1) + Whh2 @ h2(t-2)
        float acc1[2][2][4], acc2[2][2][4];
#pragma unroll
        for (int i = 0; i < 2; i++)
#pragma unroll
            for (int j = 0; j < 2; j++)
#pragma unroll
                for (int k = 0; k < 4; k++) { acc1[i][j][k] = 0.0f; acc2[i][j][k] = 0.0f; }

#pragma unroll
        for (int kt = 0; kt < 4; kt++) {
            int colb = kbase + kt * 16 + (tile >> 1) * 8;
            uint32_t a1h[2][4], a1l[2][4], a2h[2][4], a2l[2][4];
#pragma unroll
            for (int mf = 0; mf < 2; mf++) {
                int row = mf * 16 + (tile & 1) * 8 + trow;
                ldm_x4(a1h[mf], sH1hi + row * RSTRIDE + colb * 2);
                ldm_x4(a1l[mf], sH1lo + row * RSTRIDE + colb * 2);
                ldm_x4(a2h[mf], sH2hi + row * RSTRIDE + colb * 2);
                ldm_x4(a2l[mf], sH2lo + row * RSTRIDE + colb * 2);
            }
#pragma unroll
            for (int mf = 0; mf < 2; mf++)
#pragma unroll
                for (int nf = 0; nf < 2; nf++) {
                    mma_bf16(acc1[mf][nf], a1h[mf], w1h[kt][nf]);
                    mma_bf16(acc1[mf][nf], a1h[mf], w1l[kt][nf]);
                    mma_bf16(acc1[mf][nf], a1l[mf], w1h[kt][nf]);
                    mma_bf16(acc2[mf][nf], a1h[mf], w2ih[kt][nf]);
                    mma_bf16(acc2[mf][nf], a1h[mf], w2il[kt][nf]);
                    mma_bf16(acc2[mf][nf], a1l[mf], w2ih[kt][nf]);
                    mma_bf16(acc2[mf][nf], a2h[mf], w2hh[kt][nf]);
                    mma_bf16(acc2[mf][nf], a2h[mf], w2hl[kt][nf]);
                    mma_bf16(acc2[mf][nf], a2l[mf], w2hh[kt][nf]);
                }
        }

        // per-warp partials -> red1/red2 [wid][m 0..31][n 0..15]
#pragma unroll
        for (int mf = 0; mf < 2; mf++)
#pragma unroll
            for (int nf = 0; nf < 2; nf++) {
                int row = mf * 16 + (lane >> 2);
                int col = nf * 8 + (lane & 3) * 2;
                float* p0 = red1 + ((wid * 32 + row) * 18 + col);
                p0[0] = acc1[mf][nf][0]; p0[1] = acc1[mf][nf][1];
                float* p1 = red1 + ((wid * 32 + row + 8) * 18 + col);
                p1[0] = acc1[mf][nf][2]; p1[1] = acc1[mf][nf][3];
                float* q0 = red2 + ((wid * 32 + row) * 18 + col);
                q0[0] = acc2[mf][nf][0]; q0[1] = acc2[mf][nf][1];
                float* q1 = red2 + ((wid * 32 + row + 8) * 18 + col);
                q1[0] = acc2[mf][nf][2]; q1[1] = acc2[mf][nf][3];
            }
        __syncthreads();

        float h2v = 0.0f;   // for deferred hseq write
        // layer 1 update (threads 0..127), steps 0..2047
        if (tid < 128 && t < Sdim) {
            float di = x_i, df = x_f, dg = x_g, do_ = x_o;
#pragma unroll
            for (int w = 0; w < 8; w++) {
                const float* rr = red1 + (w * 32 + b) * 18;
                di  += rr[0 * 4 + jj];
                df  += rr[1 * 4 + jj];
                dg  += rr[2 * 4 + jj];
                do_ += rr[3 * 4 + jj];
            }
            float ig = 1.0f / (1.0f + __expf(-di));
            float fg = 1.0f / (1.0f + __expf(-df));
            float gg = tanhf(dg);
            float og = 1.0f / (1.0f + __expf(-do_));
            c1 = fg * c1 + ig * gg;
            float h = og * tanhf(c1);
            __nv_bfloat16 hh = __float2bfloat16_rn(h);
            __nv_bfloat16 hl = __float2bfloat16_rn(h - __bfloat162float(hh));
            g_h1b_hi[cur ^ 1][b * Hdim + j0 + jj] = hh;
            g_h1b_lo[cur ^ 1][b * Hdim + j0 + jj] = hl;
        }
        // layer 2 update (threads 128..255), computes h2(t-1), steps 1..2048
        if (tid >= 128 && t >= 1) {
            float di = bias2[0], df = bias2[1], dg = bias2[2], do_ = bias2[3];
#pragma unroll
            for (int w = 0; w < 8; w++) {
                const float* rr = red2 + (w * 32 + b) * 18;
                di  += rr[0 * 4 + jj];
                df  += rr[1 * 4 + jj];
                dg  += rr[2 * 4 + jj];
                do_ += rr[3 * 4 + jj];
            }
            float ig = 1.0f / (1.0f + __expf(-di));
            float fg = 1.0f / (1.0f + __expf(-df));
            float gg = tanhf(dg);
            float og = 1.0f / (1.0f + __expf(-do_));
            c2 = fg * c2 + ig * gg;
            h2v = og * tanhf(c2);
            __nv_bfloat16 hh = __float2bfloat16_rn(h2v);
            __nv_bfloat16 hl = __float2bfloat16_rn(h2v - __bfloat162float(hh));
            g_h2b_hi[cur ^ 1][b * Hdim + j0 + jj] = hh;
            g_h2b_lo[cur ^ 1][b * Hdim + j0 + jj] = hl;
        }
        __threadfence();   // release h1(t), h2(t-1)
        __syncthreads();

        // ARRIVE (atomic-RMW release — the validated ingredient)
        if (tid == 0) atomicAdd(&g_cnt2, 1u);

        // ---- overlap window: output writes + next-step xg prefetch ----
        if (tid >= 128 && t >= 1) {
            hseq[((size_t)b * Sdim + (t - 1)) * Hdim + j0 + jj] = h2v;
            if (t == Sdim) {
                hTo[b * Hdim + j0 + jj] = h2v;
                cTo[b * Hdim + j0 + jj] = c2;
            }
        }
        if (tid < 128 && t + 1 < Sdim) {
            xg_base += (size_t)Bdim * Gdim;
            x_i = __ldg(xg_base + 0 * Hdim);
            x_f = __ldg(xg_base + 1 * Hdim);
            x_g = __ldg(xg_base + 2 * Hdim);
            x_o = __ldg(xg_base + 3 * Hdim);
        }
    }
}

// ---------------- launch ----------------
extern "C" void kernel_launch(void* const* d_in, const int* in_sizes, int n_in,
                              void* d_out, int out_size) {
    (void)in_sizes; (void)n_in;
    const float* X   = (const float*)d_in[0];
    const float* Wih = (const float*)d_in[1];
    const float* Whh = (const float*)d_in[2];
    const float* bih = (const float*)d_in[3];
    const float* bhh = (const float*)d_in[4];
    float* out = (float*)d_out;

    size_t ht_elems = (size_t)Bdim * Sdim * Hdim;
    float* hTo = out + ht_elems;
    float* cTo = hTo + (size_t)Bdim * Hdim;

    const int smem_fused = RED2_OFF + 8 * 32 * 18 * 4;   // 169984
    const int smem_gemm  = 2 * STAGE_B;                  // 81920
    cudaFuncSetAttribute(lstm_fused,
                         cudaFuncAttributeMaxDynamicSharedMemorySize, smem_fused);
    cudaFuncSetAttribute(gemm_mma_kernel,
                         cudaFuncAttributeMaxDynamicSharedMemorySize, smem_gemm);

    conv_w_kernel<<<1024, 256>>>(Wih);                  // layer-0 Wih split
    conv_x_kernel<<<32768, 256>>>(X);

    dim3 ggrid(Gdim / 128, (Sdim * Bdim) / 128);        // (16, 512)
    gemm_mma_kernel<<<ggrid, 256, smem_gemm>>>(bih, bhh);   // layer-1 xg

    lstm_fused<<<NCTA_REC, 256, smem_fused>>>(
        Whh,                                 // Whh layer 1
        Wih + (size_t)Gdim * Hdim,           // Wih layer 2
        Whh + (size_t)Gdim * Hdim,           // Whh layer 2
        bih + Gdim, bhh + Gdim,
        out, hTo, cTo);
}

// round 15
// speedup vs baseline: 2.1482x; 1.3240x over previous
#include <cuda_runtime.h>
#include <cuda_bf16.h>
#include <cuda_fp16.h>
#include <cstdint>

#define Sdim 2048
#define Bdim 32
#define Hdim 512
#define Gdim 2048   // 4*H
#define NCTA_REC 128

typedef unsigned long long ull;

// ---------------- scratch (module-load allocated) ----------------
__device__ float g_xg [(size_t)Sdim * Bdim * Gdim];               // layer-1 gates [s*B+b][4H]
__device__ __align__(16) __nv_bfloat16 g_Ahi [(size_t)Sdim * Bdim * Hdim];
__device__ __align__(16) __nv_bfloat16 g_Alo [(size_t)Sdim * Bdim * Hdim];
__device__ __align__(16) __nv_bfloat16 g_Whi [(size_t)Gdim * Hdim];   // layer-0 Wih split
__device__ __align__(16) __nv_bfloat16 g_Wlo [(size_t)Gdim * Hdim];
__device__ __align__(16) __half g_h1b[2][Bdim * Hdim];            // ping-pong h1 (fp16)
__device__ __align__(16) __half g_h2b[2][Bdim * Hdim];            // ping-pong h2 (fp16)
__device__ unsigned g_cnt;    // init barrier
__device__ unsigned g_gen;    // init barrier
__device__ unsigned g_cnt2;   // per-step monotonic arrival counter

// ---------------- PTX helpers ----------------
__device__ __forceinline__ uint32_t smem_u32(const void* p) {
    uint32_t a;
    asm("{ .reg .u64 t; cvta.to.shared.u64 t, %1; cvt.u32.u64 %0, t; }" : "=r"(a) : "l"(p));
    return a;
}
#define CP_ASYNC16(dst, src) \
    asm volatile("cp.async.cg.shared.global [%0], [%1], 16;" :: "r"(dst), "l"(src))
#define CP_COMMIT() asm volatile("cp.async.commit_group;" ::: "memory")
#define CP_WAIT1()  asm volatile("cp.async.wait_group 1;" ::: "memory")
#define CP_WAIT0()  asm volatile("cp.async.wait_group 0;" ::: "memory")

__device__ __forceinline__ void ldm_x4(uint32_t* r, uint32_t addr) {
    asm volatile("ldmatrix.sync.aligned.m8n8.x4.shared.b16 {%0,%1,%2,%3}, [%4];"
                 : "=r"(r[0]), "=r"(r[1]), "=r"(r[2]), "=r"(r[3]) : "r"(addr));
}
__device__ __forceinline__ void mma_bf16(float* d, const uint32_t* a, const uint32_t* b) {
    asm volatile(
        "mma.sync.aligned.m16n8k16.row.col.f32.bf16.bf16.f32 "
        "{%0,%1,%2,%3}, {%4,%5,%6,%7}, {%8,%9}, {%0,%1,%2,%3};"
        : "+f"(d[0]), "+f"(d[1]), "+f"(d[2]), "+f"(d[3])
        : "r"(a[0]), "r"(a[1]), "r"(a[2]), "r"(a[3]), "r"(b[0]), "r"(b[1]));
}
__device__ __forceinline__ void mma_f16(float* d, const uint32_t* a, const uint32_t* b) {
    asm volatile(
        "mma.sync.aligned.m16n8k16.row.col.f32.f16.f16.f32 "
        "{%0,%1,%2,%3}, {%4,%5,%6,%7}, {%8,%9}, {%0,%1,%2,%3};"
        : "+f"(d[0]), "+f"(d[1]), "+f"(d[2]), "+f"(d[3])
        : "r"(a[0]), "r"(a[1]), "r"(a[2]), "r"(a[3]), "r"(b[0]), "r"(b[1]));
}

// ---------------- init grid barrier (validated; replay-safe) ----------------
__device__ __forceinline__ void grid_barrier() {
    __syncthreads();
    if (threadIdx.x == 0) {
        __threadfence();
        unsigned gen = *(volatile unsigned*)&g_gen;
        unsigned old = atomicAdd(&g_cnt, 1u);
        if (old == gridDim.x - 1) {
            atomicExch(&g_cnt, 0u);
            __threadfence();
            atomicAdd(&g_gen, 1u);
        } else {
            while (*(volatile unsigned*)&g_gen == gen) { __nanosleep(32); }
        }
        __threadfence();
    }
    __syncthreads();
}

// ---------------- fp32 -> bf16 hi/lo split (GEMM path) ----------------
__device__ __forceinline__ void split4(float4 v, ull& hi, ull& lo) {
    union { __nv_bfloat16 h[4]; ull u; } H, L;
    float f[4] = {v.x, v.y, v.z, v.w};
#pragma unroll
    for (int i = 0; i < 4; i++) {
        __nv_bfloat16 a = __float2bfloat16_rn(f[i]);
        H.h[i] = a;
        L.h[i] = __float2bfloat16_rn(f[i] - __bfloat162float(a));
    }
    hi = H.u; lo = L.u;
}
// fp32 -> fp16 hi/lo split (recurrence W path)
__device__ __forceinline__ void split4h(float4 v, ull& hi, ull& lo) {
    union { __half h[4]; ull u; } H, L;
    float f[4] = {v.x, v.y, v.z, v.w};
#pragma unroll
    for (int i = 0; i < 4; i++) {
        __half a = __float2half_rn(f[i]);
        H.h[i] = a;
        L.h[i] = __float2half_rn(f[i] - __half2float(a));
    }
    hi = H.u; lo = L.u;
}

// X[b][s][k] -> g_Ahi/g_Alo[(s*B+b)][k]
__global__ __launch_bounds__(256) void conv_x_kernel(const float* __restrict__ X) {
    size_t i = (size_t)blockIdx.x * 256 + threadIdx.x;
    int row = (int)(i >> 7);
    int c4  = (int)(i & 127);
    int b = row & 31, s = row >> 5;
    float4 v = __ldg((const float4*)(X + ((size_t)b * Sdim + s) * Hdim + c4 * 4));
    ull hi, lo;
    split4(v, hi, lo);
    *(ull*)(g_Ahi + (size_t)row * Hdim + c4 * 4) = hi;
    *(ull*)(g_Alo + (size_t)row * Hdim + c4 * 4) = lo;
}

// Wih[0][4H][H] -> g_Whi/g_Wlo (layer 0 only)
__global__ __launch_bounds__(256) void conv_w_kernel(const float* __restrict__ W) {
    size_t i = (size_t)blockIdx.x * 256 + threadIdx.x;   // 262144 float4's
    float4 v = __ldg((const float4*)W + i);
    ull hi, lo;
    split4(v, hi, lo);
    *(ull*)(g_Whi + i * 4) = hi;
    *(ull*)(g_Wlo + i * 4) = lo;
}

// ---------------- mma.sync split-bf16 GEMM (validated R4; layer-0 xg only) ----------------
#define TSTRIDE 80
#define MAT_B   (128 * TSTRIDE)
#define STAGE_B (4 * MAT_B)

__global__ __launch_bounds__(256, 1) void gemm_mma_kernel(
    const float* __restrict__ bih, const float* __restrict__ bhh)
{
    extern __shared__ char smem[];
    uint32_t sb = smem_u32(smem);
    int tid = threadIdx.x, wid = tid >> 5, lane = tid & 31;
    int col0 = blockIdx.x * 128;
    int row0 = blockIdx.y * 128;
    int wm = wid & 1, wn = wid >> 1;

    const __nv_bfloat16* a0p = g_Ahi + (size_t)row0 * Hdim;
    const __nv_bfloat16* a1p = g_Alo + (size_t)row0 * Hdim;
    const __nv_bfloat16* w0p = g_Whi + (size_t)col0 * Hdim;
    const __nv_bfloat16* w1p = g_Wlo + (size_t)col0 * Hdim;

    int ldr  = tid >> 2;
    int ldkc = tid & 3;

#define PREFETCH(stg, k0)                                                         \
    do {                                                                          \
        _Pragma("unroll")                                                         \
        for (int m = 0; m < 4; m++) {                                             \
            const __nv_bfloat16* mp = (m == 0 ? a0p : m == 1 ? a1p :              \
                                       m == 2 ? w0p : w1p);                       \
            _Pragma("unroll")                                                     \
            for (int i = 0; i < 2; i++) {                                         \
                int r = ldr + i * 64;                                             \
                uint32_t dst = sb + (stg) * STAGE_B + m * MAT_B +                 \
                               r * TSTRIDE + ldkc * 16;                           \
                const void* srcp = mp + (size_t)r * Hdim + (k0) + ldkc * 8;       \
                CP_ASYNC16(dst, srcp);                                            \
            }                                                                     \
        }                                                                         \
        CP_COMMIT();                                                              \
    } while (0)

    float acc[4][4][4];
#pragma unroll
    for (int i = 0; i < 4; i++)
#pragma unroll
        for (int j = 0; j < 4; j++)
#pragma unroll
            for (int k = 0; k < 4; k++) acc[i][j][k] = 0.0f;

    PREFETCH(0, 0);
    PREFETCH(1, 32);

    int tile = lane >> 3, trow = lane & 7;

    for (int kt = 0; kt < 16; kt++) {
        if (kt == 15) CP_WAIT0(); else CP_WAIT1();
        __syncthreads();
        uint32_t base = sb + (kt & 1) * STAGE_B;

#pragma unroll
        for (int ks = 0; ks < 2; ks++) {
            uint32_t ahi[4][4], alo[4][4];
#pragma unroll
            for (int mf = 0; mf < 4; mf++) {
                int row = wm * 64 + mf * 16 + (tile & 1) * 8 + trow;
                int col = ks * 16 + (tile >> 1) * 8;
                ldm_x4(ahi[mf], base + 0 * MAT_B + row * TSTRIDE + col * 2);
                ldm_x4(alo[mf], base + 1 * MAT_B + row * TSTRIDE + col * 2);
            }
            uint32_t bhi[4][2], blo[4][2];
#pragma unroll
            for (int p = 0; p < 2; p++) {
                int rn = wn * 32 + p * 16 + (tile >> 1) * 8 + trow;
                int ck = ks * 16 + (tile & 1) * 8;
                uint32_t r4[4];
                ldm_x4(r4, base + 2 * MAT_B + rn * TSTRIDE + ck * 2);
                bhi[2*p][0] = r4[0]; bhi[2*p][1] = r4[1];
                bhi[2*p+1][0] = r4[2]; bhi[2*p+1][1] = r4[3];
                ldm_x4(r4, base + 3 * MAT_B + rn * TSTRIDE + ck * 2);
                blo[2*p][0] = r4[0]; blo[2*p][1] = r4[1];
                blo[2*p+1][0] = r4[2]; blo[2*p+1][1] = r4[3];
            }
#pragma unroll
            for (int mf = 0; mf < 4; mf++)
#pragma unroll
                for (int nf = 0; nf < 4; nf++) {
                    mma_bf16(acc[mf][nf], ahi[mf], bhi[nf]);
                    mma_bf16(acc[mf][nf], ahi[mf], blo[nf]);
                    mma_bf16(acc[mf][nf], alo[mf], bhi[nf]);
                }
        }
        __syncthreads();
        if (kt < 14) PREFETCH(kt & 1, (kt + 2) * 32);
    }

#pragma unroll
    for (int mf = 0; mf < 4; mf++) {
        int r0 = row0 + wm * 64 + mf * 16 + (lane >> 2);
#pragma unroll
        for (int nf = 0; nf < 4; nf++) {
            int cb = col0 + wn * 32 + nf * 8 + 2 * (lane & 3);
            float b0v = __ldg(&bih[cb])     + __ldg(&bhh[cb]);
            float b1v = __ldg(&bih[cb + 1]) + __ldg(&bhh[cb + 1]);
            *(float2*)&g_xg[(size_t)r0 * Gdim + cb] =
                make_float2(acc[mf][nf][0] + b0v, acc[mf][nf][1] + b1v);
            *(float2*)&g_xg[(size_t)(r0 + 8) * Gdim + cb] =
                make_float2(acc[mf][nf][2] + b0v, acc[mf][nf][3] + b1v);
        }
    }
#undef PREFETCH
}

// ---------------- fused 2-layer wavefront recurrence (fp16 h, split-fp16 W) ----------------
// 128 CTAs x 256 threads. CTA owns hidden units j0..j0+3 of BOTH layers.
// h stored as single fp16 (error ~1e-4 via half-ulp rounding); W split fp16 (exact).
// Per-warp staging: warp w copies only cols [w*64, w*64+64) of h1/h2 (8KB),
// waits its own cp.async group + __syncwarp — warp smem slices are disjoint.
#define RSTRIDE 1040                     // bytes per smem 16-bit row of 512 (+pad)
#define RED1_OFF (64 * RSTRIDE)          // 66560 (sH1+sH2; also W staging at init)
#define RED2_OFF (RED1_OFF + 8*32*18*4)  // +18432

__global__ __launch_bounds__(256, 1) void lstm_fused(
    const float* __restrict__ Whh1, const float* __restrict__ Wih2,
    const float* __restrict__ Whh2,
    const float* __restrict__ bih2, const float* __restrict__ bhh2,
    float* __restrict__ hseq, float* __restrict__ hTo, float* __restrict__ cTo)
{
    extern __shared__ char sm[];
    uint32_t sb = smem_u32(sm);
    uint32_t sH1 = sb;                    // [32 rows] fp16 h1 (init: W-hi staging)
    uint32_t sH2 = sb + 32 * RSTRIDE;     // [32 rows] fp16 h2 (init: W-lo staging)
    float* red1 = (float*)(sm + RED1_OFF);   // [8][32][18]
    float* red2 = (float*)(sm + RED2_OFF);   // [8][32][18]

    int tid = threadIdx.x, wid = tid >> 5, lane = tid & 31;
    int b  = tid & 31;
    int jj = (tid >> 5) & 3;
    int j0 = blockIdx.x * 4;

    int kbase = wid * 64;
    int tile = lane >> 3, trow = lane & 7;

    // ---- init: load 3 W-frag sets (split fp16) via smem staging ----
    uint32_t w1h[4][2][2],  w1l[4][2][2];
    uint32_t w2ih[4][2][2], w2il[4][2][2];
    uint32_t w2hh[4][2][2], w2hl[4][2][2];

#define LOAD_WFRAGS(Wsrc, Fh, Fl)                                                  \
    do {                                                                           \
        for (int idx = tid; idx < 2048; idx += 256) {                              \
            int r = idx >> 7, c4 = idx & 127;                                      \
            int q = r >> 2, j = r & 3;                                             \
            float4 v = __ldg((const float4*)((Wsrc) +                              \
                        (size_t)(q * Hdim + j0 + j) * Hdim + c4 * 4));             \
            ull hi, lo;                                                            \
            split4h(v, hi, lo);                                                    \
            *(ull*)(sm + r * RSTRIDE + c4 * 8) = hi;                               \
            *(ull*)(sm + 32 * RSTRIDE + r * RSTRIDE + c4 * 8) = lo;                \
        }                                                                          \
        __syncthreads();                                                           \
        _Pragma("unroll")                                                          \
        for (int kt = 0; kt < 4; kt++) {                                           \
            int row = (tile >> 1) * 8 + trow;                                      \
            int col = kbase + kt * 16 + (tile & 1) * 8;                            \
            uint32_t r4[4];                                                        \
            ldm_x4(r4, sH1 + row * RSTRIDE + col * 2);                             \
            Fh[kt][0][0] = r4[0]; Fh[kt][0][1] = r4[1];                            \
            Fh[kt][1][0] = r4[2]; Fh[kt][1][1] = r4[3];                            \
            ldm_x4(r4, sH2 + row * RSTRIDE + col * 2);                             \
            Fl[kt][0][0] = r4[0]; Fl[kt][0][1] = r4[1];                            \
            Fl[kt][1][0] = r4[2]; Fl[kt][1][1] = r4[3];                            \
        }                                                                          \
        __syncthreads();                                                           \
    } while (0)

    LOAD_WFRAGS(Whh1, w1h,  w1l);
    LOAD_WFRAGS(Wih2, w2ih, w2il);
    LOAD_WFRAGS(Whh2, w2hh, w2hl);
#undef LOAD_WFRAGS

    // layer-2 per-thread bias (gate cols q*512 + j0+jj)
    float bias2[4];
#pragma unroll
    for (int q = 0; q < 4; q++)
        bias2[q] = __ldg(&bih2[q * Hdim + j0 + jj]) + __ldg(&bhh2[q * Hdim + j0 + jj]);

    if (blockIdx.x == 0 && tid == 0) g_cnt2 = 0u;
    if (tid < 128) {   // h1(-1)=0 in buf[0]; h2(-1)=0 in buf[1]
        g_h1b[0][b * Hdim + j0 + jj] = __float2half(0.0f);
        g_h2b[1][b * Hdim + j0 + jj] = __float2half(0.0f);
        // also zero h2 buf[0] so step-0's (discarded) MMA reads defined data
        g_h2b[0][b * Hdim + j0 + jj] = __float2half(0.0f);
    }
    grid_barrier();   // zeros + counter reset visible everywhere

    float c1 = 0.0f, c2 = 0.0f;
    const float* xg_base = g_xg + (size_t)b * Gdim + (j0 + jj);
    float x_i = __ldg(xg_base + 0 * Hdim);
    float x_f = __ldg(xg_base + 1 * Hdim);
    float x_g = __ldg(xg_base + 2 * Hdim);
    float x_o = __ldg(xg_base + 3 * Hdim);

    for (int t = 0; t <= Sdim; t++) {
        int cur = t & 1;

        // WAIT: all CTAs completed step t-1
        if (t > 0) {
            if (tid == 0) {
                unsigned target = (unsigned)t * NCTA_REC;
                while (*(volatile unsigned*)&g_cnt2 < target) { }
                __threadfence();
            }
            __syncthreads();
        }

        // per-warp stage: own k-slice of h1(t-1), h2(t-2): 2 x 4KB
        {
            const char* s1 = (const char*)g_h1b[cur];
            const char* s2 = (const char*)g_h2b[cur];
            int colbyte = wid * 128;   // 64 fp16
#pragma unroll
            for (int i = 0; i < 8; i++) {
                int c = lane + i * 32;            // 0..255
                int r = c >> 3, ch = c & 7;
                uint32_t off = r * RSTRIDE + colbyte + ch * 16;
                int goff = r * 1024 + colbyte + ch * 16;
                CP_ASYNC16(sH1 + off, s1 + goff);
                CP_ASYNC16(sH2 + off, s2 + goff);
            }
        }
        CP_COMMIT();
        CP_WAIT0();
        __syncwarp();

        // MMA: acc1 = Whh1 @ h1(t-1); acc2 = Wih2 @ h1(t-1) + Whh2 @ h2(t-2)
        float acc1[2][2][4], acc2[2][2][4];
#pragma unroll
        for (int i = 0; i < 2; i++)
#pragma unroll
            for (int j = 0; j < 2; j++)
#pragma unroll
                for (int k = 0; k < 4; k++) { acc1[i][j][k] = 0.0f; acc2[i][j][k] = 0.0f; }

#pragma unroll
        for (int kt = 0; kt < 4; kt++) {
            int colb = kbase + kt * 16 + (tile >> 1) * 8;
            uint32_t a1[2][4], a2[2][4];
#pragma unroll
            for (int mf = 0; mf < 2; mf++) {
                int row = mf * 16 + (tile & 1) * 8 + trow;
                ldm_x4(a1[mf], sH1 + row * RSTRIDE + colb * 2);
                ldm_x4(a2[mf], sH2 + row * RSTRIDE + colb * 2);
            }
#pragma unroll
            for (int mf = 0; mf < 2; mf++)
#pragma unroll
                for (int nf = 0; nf < 2; nf++) {
                    mma_f16(acc1[mf][nf], a1[mf], w1h[kt][nf]);
                    mma_f16(acc1[mf][nf], a1[mf], w1l[kt][nf]);
                    mma_f16(acc2[mf][nf], a1[mf], w2ih[kt][nf]);
                    mma_f16(acc2[mf][nf], a1[mf], w2il[kt][nf]);
                    mma_f16(acc2[mf][nf], a2[mf], w2hh[kt][nf]);
                    mma_f16(acc2[mf][nf], a2[mf], w2hl[kt][nf]);
                }
        }

        // per-warp partials -> red1/red2 [wid][m 0..31][n 0..15]
#pragma unroll
        for (int mf = 0; mf < 2; mf++)
#pragma unroll
            for (int nf = 0; nf < 2; nf++) {
                int row = mf * 16 + (lane >> 2);
                int col = nf * 8 + (lane & 3) * 2;
                float* p0 = red1 + ((wid * 32 + row) * 18 + col);
                p0[0] = acc1[mf][nf][0]; p0[1] = acc1[mf][nf][1];
                float* p1 = red1 + ((wid * 32 + row + 8) * 18 + col);
                p1[0] = acc1[mf][nf][2]; p1[1] = acc1[mf][nf][3];
                float* q0 = red2 + ((wid * 32 + row) * 18 + col);
                q0[0] = acc2[mf][nf][0]; q0[1] = acc2[mf][nf][1];
                float* q1 = red2 + ((wid * 32 + row + 8) * 18 + col);
                q1[0] = acc2[mf][nf][2]; q1[1] = acc2[mf][nf][3];
            }
        __syncthreads();

        float h2v = 0.0f;   // for deferred hseq write
        // layer 1 update (threads 0..127), steps 0..2047
        if (tid < 128 && t < Sdim) {
            float di = x_i, df = x_f, dg = x_g, do_ = x_o;
#pragma unroll
            for (int w = 0; w < 8; w++) {
                const float* rr = red1 + (w * 32 + b) * 18;
                di  += rr[0 * 4 + jj];
                df  += rr[1 * 4 + jj];
                dg  += rr[2 * 4 + jj];
                do_ += rr[3 * 4 + jj];
            }
            float ig = 1.0f / (1.0f + __expf(-di));
            float fg = 1.0f / (1.0f + __expf(-df));
            float gg = tanhf(dg);
            float og = 1.0f / (1.0f + __expf(-do_));
            c1 = fg * c1 + ig * gg;
            float h = og * tanhf(c1);
            g_h1b[cur ^ 1][b * Hdim + j0 + jj] = __float2half_rn(h);
        }
        // layer 2 update (threads 128..255), computes h2(t-1), steps 1..2048
        if (tid >= 128 && t >= 1) {
            float di = bias2[0], df = bias2[1], dg = bias2[2], do_ = bias2[3];
#pragma unroll
            for (int w = 0; w < 8; w++) {
                const float* rr = red2 + (w * 32 + b) * 18;
                di  += rr[0 * 4 + jj];
                df  += rr[1 * 4 + jj];
                dg  += rr[2 * 4 + jj];
                do_ += rr[3 * 4 + jj];
            }
            float ig = 1.0f / (1.0f + __expf(-di));
            float fg = 1.0f / (1.0f + __expf(-df));
            float gg = tanhf(dg);
            float og = 1.0f / (1.0f + __expf(-do_));
            c2 = fg * c2 + ig * gg;
            h2v = og * tanhf(c2);
            g_h2b[cur ^ 1][b * Hdim + j0 + jj] = __float2half_rn(h2v);
        }
        __threadfence();   // release h1(t), h2(t-1)
        __syncthreads();

        // ARRIVE (atomic-RMW release — the validated ingredient)
        if (tid == 0) atomicAdd(&g_cnt2, 1u);

        // ---- overlap window: output writes + next-step xg prefetch ----
        if (tid >= 128 && t >= 1) {
            hseq[((size_t)b * Sdim + (t - 1)) * Hdim + j0 + jj] = h2v;
            if (t == Sdim) {
                hTo[b * Hdim + j0 + jj] = h2v;
                cTo[b * Hdim + j0 + jj] = c2;
            }
        }
        if (tid < 128 && t + 1 < Sdim) {
            xg_base += (size_t)Bdim * Gdim;
            x_i = __ldg(xg_base + 0 * Hdim);
            x_f = __ldg(xg_base + 1 * Hdim);
            x_g = __ldg(xg_base + 2 * Hdim);
            x_o = __ldg(xg_base + 3 * Hdim);
        }
    }
}

// ---------------- launch ----------------
extern "C" void kernel_launch(void* const* d_in, const int* in_sizes, int n_in,
                              void* d_out, int out_size) {
    (void)in_sizes; (void)n_in;
    const float* X   = (const float*)d_in[0];
    const float* Wih = (const float*)d_in[1];
    const float* Whh = (const float*)d_in[2];
    const float* bih = (const float*)d_in[3];
    const float* bhh = (const float*)d_in[4];
    float* out = (float*)d_out;

    size_t ht_elems = (size_t)Bdim * Sdim * Hdim;
    float* hTo = out + ht_elems;
    float* cTo = hTo + (size_t)Bdim * Hdim;

    const int smem_fused = RED2_OFF + 8 * 32 * 18 * 4;   // 103424
    const int smem_gemm  = 2 * STAGE_B;                  // 81920
    cudaFuncSetAttribute(lstm_fused,
                         cudaFuncAttributeMaxDynamicSharedMemorySize, smem_fused);
    cudaFuncSetAttribute(gemm_mma_kernel,
                         cudaFuncAttributeMaxDynamicSharedMemorySize, smem_gemm);

    conv_w_kernel<<<1024, 256>>>(Wih);                  // layer-0 Wih split
    conv_x_kernel<<<32768, 256>>>(X);

    dim3 ggrid(Gdim / 128, (Sdim * Bdim) / 128);        // (16, 512)
    gemm_mma_kernel<<<ggrid, 256, smem_gemm>>>(bih, bhh);   // layer-1 xg

    lstm_fused<<<NCTA_REC, 256, smem_fused>>>(
        Whh,                                 // Whh layer 1
        Wih + (size_t)Gdim * Hdim,           // Wih layer 2
        Whh + (size_t)Gdim * Hdim,           // Whh layer 2
        bih + Gdim, bhh + Gdim,
        out, hTo, cTo);
}

// round 16
// speedup vs baseline: 2.3151x; 1.0777x over previous
#include <cuda_runtime.h>
#include <cuda_bf16.h>
#include <cuda_fp16.h>
#include <cstdint>

#define Sdim 2048
#define Bdim 32
#define Hdim 512
#define Gdim 2048   // 4*H
#define NCTA_REC 128
#define NSTRIPE 8
#define STRIDEW 64   // unsigned words between stripes (256B)

typedef unsigned long long ull;

// ---------------- scratch (module-load allocated) ----------------
__device__ float g_xg [(size_t)Sdim * Bdim * Gdim];               // layer-1 gates [s*B+b][4H]
__device__ __align__(16) __nv_bfloat16 g_Ahi [(size_t)Sdim * Bdim * Hdim];
__device__ __align__(16) __nv_bfloat16 g_Alo [(size_t)Sdim * Bdim * Hdim];
__device__ __align__(16) __nv_bfloat16 g_Whi [(size_t)Gdim * Hdim];   // layer-0 Wih split
__device__ __align__(16) __nv_bfloat16 g_Wlo [(size_t)Gdim * Hdim];
__device__ __align__(16) __half g_h1b[2][Bdim * Hdim];            // ping-pong h1 (fp16)
__device__ __align__(16) __half g_h2b[2][Bdim * Hdim];            // ping-pong h2 (fp16)
__device__ unsigned g_cnt;    // init barrier
__device__ unsigned g_gen;    // init barrier
__device__ __align__(256) unsigned g_cntS[NSTRIPE * STRIDEW];   // striped arrival counters

// ---------------- PTX helpers ----------------
__device__ __forceinline__ uint32_t smem_u32(const void* p) {
    uint32_t a;
    asm("{ .reg .u64 t; cvta.to.shared.u64 t, %1; cvt.u32.u64 %0, t; }" : "=r"(a) : "l"(p));
    return a;
}
#define CP_ASYNC16(dst, src) \
    asm volatile("cp.async.cg.shared.global [%0], [%1], 16;" :: "r"(dst), "l"(src))
#define CP_COMMIT() asm volatile("cp.async.commit_group;" ::: "memory")
#define CP_WAIT1()  asm volatile("cp.async.wait_group 1;" ::: "memory")
#define CP_WAIT0()  asm volatile("cp.async.wait_group 0;" ::: "memory")

__device__ __forceinline__ void ldm_x4(uint32_t* r, uint32_t addr) {
    asm volatile("ldmatrix.sync.aligned.m8n8.x4.shared.b16 {%0,%1,%2,%3}, [%4];"
                 : "=r"(r[0]), "=r"(r[1]), "=r"(r[2]), "=r"(r[3]) : "r"(addr));
}
__device__ __forceinline__ void mma_bf16(float* d, const uint32_t* a, const uint32_t* b) {
    asm volatile(
        "mma.sync.aligned.m16n8k16.row.col.f32.bf16.bf16.f32 "
        "{%0,%1,%2,%3}, {%4,%5,%6,%7}, {%8,%9}, {%0,%1,%2,%3};"
        : "+f"(d[0]), "+f"(d[1]), "+f"(d[2]), "+f"(d[3])
        : "r"(a[0]), "r"(a[1]), "r"(a[2]), "r"(a[3]), "r"(b[0]), "r"(b[1]));
}
__device__ __forceinline__ void mma_f16(float* d, const uint32_t* a, const uint32_t* b) {
    asm volatile(
        "mma.sync.aligned.m16n8k16.row.col.f32.f16.f16.f32 "
        "{%0,%1,%2,%3}, {%4,%5,%6,%7}, {%8,%9}, {%0,%1,%2,%3};"
        : "+f"(d[0]), "+f"(d[1]), "+f"(d[2]), "+f"(d[3])
        : "r"(a[0]), "r"(a[1]), "r"(a[2]), "r"(a[3]), "r"(b[0]), "r"(b[1]));
}

// ---------------- init grid barrier (validated; replay-safe) ----------------
__device__ __forceinline__ void grid_barrier() {
    __syncthreads();
    if (threadIdx.x == 0) {
        __threadfence();
        unsigned gen = *(volatile unsigned*)&g_gen;
        unsigned old = atomicAdd(&g_cnt, 1u);
        if (old == gridDim.x - 1) {
            atomicExch(&g_cnt, 0u);
            __threadfence();
            atomicAdd(&g_gen, 1u);
        } else {
            while (*(volatile unsigned*)&g_gen == gen) { __nanosleep(32); }
        }
        __threadfence();
    }
    __syncthreads();
}

// ---------------- fp32 -> bf16 hi/lo split (GEMM path) ----------------
__device__ __forceinline__ void split4(float4 v, ull& hi, ull& lo) {
    union { __nv_bfloat16 h[4]; ull u; } H, L;
    float f[4] = {v.x, v.y, v.z, v.w};
#pragma unroll
    for (int i = 0; i < 4; i++) {
        __nv_bfloat16 a = __float2bfloat16_rn(f[i]);
        H.h[i] = a;
        L.h[i] = __float2bfloat16_rn(f[i] - __bfloat162float(a));
    }
    hi = H.u; lo = L.u;
}
// fp32 -> fp16 hi/lo split (recurrence W path)
__device__ __forceinline__ void split4h(float4 v, ull& hi, ull& lo) {
    union { __half h[4]; ull u; } H, L;
    float f[4] = {v.x, v.y, v.z, v.w};
#pragma unroll
    for (int i = 0; i < 4; i++) {
        __half a = __float2half_rn(f[i]);
        H.h[i] = a;
        L.h[i] = __float2half_rn(f[i] - __half2float(a));
    }
    hi = H.u; lo = L.u;
}

// X[b][s][k] -> g_Ahi/g_Alo[(s*B+b)][k]
__global__ __launch_bounds__(256) void conv_x_kernel(const float* __restrict__ X) {
    size_t i = (size_t)blockIdx.x * 256 + threadIdx.x;
    int row = (int)(i >> 7);
    int c4  = (int)(i & 127);
    int b = row & 31, s = row >> 5;
    float4 v = __ldg((const float4*)(X + ((size_t)b * Sdim + s) * Hdim + c4 * 4));
    ull hi, lo;
    split4(v, hi, lo);
    *(ull*)(g_Ahi + (size_t)row * Hdim + c4 * 4) = hi;
    *(ull*)(g_Alo + (size_t)row * Hdim + c4 * 4) = lo;
}

// Wih[0][4H][H] -> g_Whi/g_Wlo (layer 0 only)
__global__ __launch_bounds__(256) void conv_w_kernel(const float* __restrict__ W) {
    size_t i = (size_t)blockIdx.x * 256 + threadIdx.x;   // 262144 float4's
    float4 v = __ldg((const float4*)W + i);
    ull hi, lo;
    split4(v, hi, lo);
    *(ull*)(g_Whi + i * 4) = hi;
    *(ull*)(g_Wlo + i * 4) = lo;
}

// ---------------- mma.sync split-bf16 GEMM (validated R4; layer-0 xg only) ----------------
#define TSTRIDE 80
#define MAT_B   (128 * TSTRIDE)
#define STAGE_B (4 * MAT_B)

__global__ __launch_bounds__(256, 1) void gemm_mma_kernel(
    const float* __restrict__ bih, const float* __restrict__ bhh)
{
    extern __shared__ char smem[];
    uint32_t sb = smem_u32(smem);
    int tid = threadIdx.x, wid = tid >> 5, lane = tid & 31;
    int col0 = blockIdx.x * 128;
    int row0 = blockIdx.y * 128;
    int wm = wid & 1, wn = wid >> 1;

    const __nv_bfloat16* a0p = g_Ahi + (size_t)row0 * Hdim;
    const __nv_bfloat16* a1p = g_Alo + (size_t)row0 * Hdim;
    const __nv_bfloat16* w0p = g_Whi + (size_t)col0 * Hdim;
    const __nv_bfloat16* w1p = g_Wlo + (size_t)col0 * Hdim;

    int ldr  = tid >> 2;
    int ldkc = tid & 3;

#define PREFETCH(stg, k0)                                                         \
    do {                                                                          \
        _Pragma("unroll")                                                         \
        for (int m = 0; m < 4; m++) {                                             \
            const __nv_bfloat16* mp = (m == 0 ? a0p : m == 1 ? a1p :              \
                                       m == 2 ? w0p : w1p);                       \
            _Pragma("unroll")                                                     \
            for (int i = 0; i < 2; i++) {                                         \
                int r = ldr + i * 64;                                             \
                uint32_t dst = sb + (stg) * STAGE_B + m * MAT_B +                 \
                               r * TSTRIDE + ldkc * 16;                           \
                const void* srcp = mp + (size_t)r * Hdim + (k0) + ldkc * 8;       \
                CP_ASYNC16(dst, srcp);                                            \
            }                                                                     \
        }                                                                         \
        CP_COMMIT();                                                              \
    } while (0)

    float acc[4][4][4];
#pragma unroll
    for (int i = 0; i < 4; i++)
#pragma unroll
        for (int j = 0; j < 4; j++)
#pragma unroll
            for (int k = 0; k < 4; k++) acc[i][j][k] = 0.0f;

    PREFETCH(0, 0);
    PREFETCH(1, 32);

    int tile = lane >> 3, trow = lane & 7;

    for (int kt = 0; kt < 16; kt++) {
        if (kt == 15) CP_WAIT0(); else CP_WAIT1();
        __syncthreads();
        uint32_t base = sb + (kt & 1) * STAGE_B;

#pragma unroll
        for (int ks = 0; ks < 2; ks++) {
            uint32_t ahi[4][4], alo[4][4];
#pragma unroll
            for (int mf = 0; mf < 4; mf++) {
                int row = wm * 64 + mf * 16 + (tile & 1) * 8 + trow;
                int col = ks * 16 + (tile >> 1) * 8;
                ldm_x4(ahi[mf], base + 0 * MAT_B + row * TSTRIDE + col * 2);
                ldm_x4(alo[mf], base + 1 * MAT_B + row * TSTRIDE + col * 2);
            }
            uint32_t bhi[4][2], blo[4][2];
#pragma unroll
            for (int p = 0; p < 2; p++) {
                int rn = wn * 32 + p * 16 + (tile >> 1) * 8 + trow;
                int ck = ks * 16 + (tile & 1) * 8;
                uint32_t r4[4];
                ldm_x4(r4, base + 2 * MAT_B + rn * TSTRIDE + ck * 2);
                bhi[2*p][0] = r4[0]; bhi[2*p][1] = r4[1];
                bhi[2*p+1][0] = r4[2]; bhi[2*p+1][1] = r4[3];
                ldm_x4(r4, base + 3 * MAT_B + rn * TSTRIDE + ck * 2);
                blo[2*p][0] = r4[0]; blo[2*p][1] = r4[1];
                blo[2*p+1][0] = r4[2]; blo[2*p+1][1] = r4[3];
            }
#pragma unroll
            for (int mf = 0; mf < 4; mf++)
#pragma unroll
                for (int nf = 0; nf < 4; nf++) {
                    mma_bf16(acc[mf][nf], ahi[mf], bhi[nf]);
                    mma_bf16(acc[mf][nf], ahi[mf], blo[nf]);
                    mma_bf16(acc[mf][nf], alo[mf], bhi[nf]);
                }
        }
        __syncthreads();
        if (kt < 14) PREFETCH(kt & 1, (kt + 2) * 32);
    }

#pragma unroll
    for (int mf = 0; mf < 4; mf++) {
        int r0 = row0 + wm * 64 + mf * 16 + (lane >> 2);
#pragma unroll
        for (int nf = 0; nf < 4; nf++) {
            int cb = col0 + wn * 32 + nf * 8 + 2 * (lane & 3);
            float b0v = __ldg(&bih[cb])     + __ldg(&bhh[cb]);
            float b1v = __ldg(&bih[cb + 1]) + __ldg(&bhh[cb + 1]);
            *(float2*)&g_xg[(size_t)r0 * Gdim + cb] =
                make_float2(acc[mf][nf][0] + b0v, acc[mf][nf][1] + b1v);
            *(float2*)&g_xg[(size_t)(r0 + 8) * Gdim + cb] =
                make_float2(acc[mf][nf][2] + b0v, acc[mf][nf][3] + b1v);
        }
    }
#undef PREFETCH
}

// ---------------- fused 2-layer wavefront recurrence (fp16 h, split-fp16 W) ----------------
// 128 CTAs x 256 threads. CTA owns hidden units j0..j0+3 of BOTH layers.
// Striped arrival counters: CTA i arrives on stripe i&7 (atomicAdd); waiters
// (lanes 0..7 of warp 0) each poll one stripe for >= t*16.
#define RSTRIDE 1040                     // bytes per smem 16-bit row of 512 (+pad)
#define RED1_OFF (64 * RSTRIDE)          // 66560 (sH1+sH2; also W staging at init)
#define RED2_OFF (RED1_OFF + 8*32*18*4)  // +18432

__global__ __launch_bounds__(256, 1) void lstm_fused(
    const float* __restrict__ Whh1, const float* __restrict__ Wih2,
    const float* __restrict__ Whh2,
    const float* __restrict__ bih2, const float* __restrict__ bhh2,
    float* __restrict__ hseq, float* __restrict__ hTo, float* __restrict__ cTo)
{
    extern __shared__ char sm[];
    uint32_t sb = smem_u32(sm);
    uint32_t sH1 = sb;                    // [32 rows] fp16 h1 (init: W-hi staging)
    uint32_t sH2 = sb + 32 * RSTRIDE;     // [32 rows] fp16 h2 (init: W-lo staging)
    float* red1 = (float*)(sm + RED1_OFF);   // [8][32][18]
    float* red2 = (float*)(sm + RED2_OFF);   // [8][32][18]

    int tid = threadIdx.x, wid = tid >> 5, lane = tid & 31;
    int b  = tid & 31;
    int jj = (tid >> 5) & 3;
    int j0 = blockIdx.x * 4;
    int stripe = blockIdx.x & (NSTRIPE - 1);

    int kbase = wid * 64;
    int tile = lane >> 3, trow = lane & 7;

    // ---- init: load 3 W-frag sets (split fp16) via smem staging ----
    uint32_t w1h[4][2][2],  w1l[4][2][2];
    uint32_t w2ih[4][2][2], w2il[4][2][2];
    uint32_t w2hh[4][2][2], w2hl[4][2][2];

#define LOAD_WFRAGS(Wsrc, Fh, Fl)                                                  \
    do {                                                                           \
        for (int idx = tid; idx < 2048; idx += 256) {                              \
            int r = idx >> 7, c4 = idx & 127;                                      \
            int q = r >> 2, j = r & 3;                                             \
            float4 v = __ldg((const float4*)((Wsrc) +                              \
                        (size_t)(q * Hdim + j0 + j) * Hdim + c4 * 4));             \
            ull hi, lo;                                                            \
            split4h(v, hi, lo);                                                    \
            *(ull*)(sm + r * RSTRIDE + c4 * 8) = hi;                               \
            *(ull*)(sm + 32 * RSTRIDE + r * RSTRIDE + c4 * 8) = lo;                \
        }                                                                          \
        __syncthreads();                                                           \
        _Pragma("unroll")                                                          \
        for (int kt = 0; kt < 4; kt++) {                                           \
            int row = (tile >> 1) * 8 + trow;                                      \
            int col = kbase + kt * 16 + (tile & 1) * 8;                            \
            uint32_t r4[4];                                                        \
            ldm_x4(r4, sH1 + row * RSTRIDE + col * 2);                             \
            Fh[kt][0][0] = r4[0]; Fh[kt][0][1] = r4[1];                            \
            Fh[kt][1][0] = r4[2]; Fh[kt][1][1] = r4[3];                            \
            ldm_x4(r4, sH2 + row * RSTRIDE + col * 2);                             \
            Fl[kt][0][0] = r4[0]; Fl[kt][0][1] = r4[1];                            \
            Fl[kt][1][0] = r4[2]; Fl[kt][1][1] = r4[3];                            \
        }                                                                          \
        __syncthreads();                                                           \
    } while (0)

    LOAD_WFRAGS(Whh1, w1h,  w1l);
    LOAD_WFRAGS(Wih2, w2ih, w2il);
    LOAD_WFRAGS(Whh2, w2hh, w2hl);
#undef LOAD_WFRAGS

    // layer-2 per-thread bias (gate cols q*512 + j0+jj)
    float bias2[4];
#pragma unroll
    for (int q = 0; q < 4; q++)
        bias2[q] = __ldg(&bih2[q * Hdim + j0 + jj]) + __ldg(&bhh2[q * Hdim + j0 + jj]);

    if (blockIdx.x == 0 && tid < NSTRIPE) g_cntS[tid * STRIDEW] = 0u;
    if (tid < 128) {   // h1(-1)=0 in buf[0]; h2(-1)=0 in buf[1]; also h2 buf[0] defined
        g_h1b[0][b * Hdim + j0 + jj] = __float2half(0.0f);
        g_h2b[1][b * Hdim + j0 + jj] = __float2half(0.0f);
        g_h2b[0][b * Hdim + j0 + jj] = __float2half(0.0f);
    }
    grid_barrier();   // zeros + counter resets visible everywhere

    float c1 = 0.0f, c2 = 0.0f;
    const float* xg_base = g_xg + (size_t)b * Gdim + (j0 + jj);
    float x_i = __ldg(xg_base + 0 * Hdim);
    float x_f = __ldg(xg_base + 1 * Hdim);
    float x_g = __ldg(xg_base + 2 * Hdim);
    float x_o = __ldg(xg_base + 3 * Hdim);

    for (int t = 0; t <= Sdim; t++) {
        int cur = t & 1;

        // WAIT: all CTAs arrived t times. Lanes 0..7 of warp 0 poll one stripe each.
        if (t > 0) {
            if (tid < NSTRIPE) {
                unsigned target = (unsigned)t * (NCTA_REC / NSTRIPE);
                while (*(volatile unsigned*)&g_cntS[tid * STRIDEW] < target) { }
            }
            if (wid == 0) __threadfence();   // acquire (one MEMBAR for the polling warp)
            __syncthreads();
        }

        // per-warp stage: own k-slice of h1(t-1), h2(t-2): 2 x 4KB
        {
            const char* s1 = (const char*)g_h1b[cur];
            const char* s2 = (const char*)g_h2b[cur];
            int colbyte = wid * 128;   // 64 fp16
#pragma unroll
            for (int i = 0; i < 8; i++) {
                int c = lane + i * 32;            // 0..255
                int r = c >> 3, ch = c & 7;
                uint32_t off = r * RSTRIDE + colbyte + ch * 16;
                int goff = r * 1024 + colbyte + ch * 16;
                CP_ASYNC16(sH1 + off, s1 + goff);
                CP_ASYNC16(sH2 + off, s2 + goff);
            }
        }
        CP_COMMIT();
        CP_WAIT0();
        __syncwarp();

        // MMA: acc1 = Whh1 @ h1(t-1); acc2 = Wih2 @ h1(t-1) + Whh2 @ h2(t-2)
        float acc1[2][2][4], acc2[2][2][4];
#pragma unroll
        for (int i = 0; i < 2; i++)
#pragma unroll
            for (int j = 0; j < 2; j++)
#pragma unroll
                for (int k = 0; k < 4; k++) { acc1[i][j][k] = 0.0f; acc2[i][j][k] = 0.0f; }

#pragma unroll
        for (int kt = 0; kt < 4; kt++) {
            int colb = kbase + kt * 16 + (tile >> 1) * 8;
            uint32_t a1[2][4], a2[2][4];
#pragma unroll
            for (int mf = 0; mf < 2; mf++) {
                int row = mf * 16 + (tile & 1) * 8 + trow;
                ldm_x4(a1[mf], sH1 + row * RSTRIDE + colb * 2);
                ldm_x4(a2[mf], sH2 + row * RSTRIDE + colb * 2);
            }
#pragma unroll
            for (int mf = 0; mf < 2; mf++)
#pragma unroll
                for (int nf = 0; nf < 2; nf++) {
                    mma_f16(acc1[mf][nf], a1[mf], w1h[kt][nf]);
                    mma_f16(acc1[mf][nf], a1[mf], w1l[kt][nf]);
                    mma_f16(acc2[mf][nf], a1[mf], w2ih[kt][nf]);
                    mma_f16(acc2[mf][nf], a1[mf], w2il[kt][nf]);
                    mma_f16(acc2[mf][nf], a2[mf], w2hh[kt][nf]);
                    mma_f16(acc2[mf][nf], a2[mf], w2hl[kt][nf]);
                }
        }

        // per-warp partials -> red1/red2 [wid][m 0..31][n 0..15]
#pragma unroll
        for (int mf = 0; mf < 2; mf++)
#pragma unroll
            for (int nf = 0; nf < 2; nf++) {
                int row = mf * 16 + (lane >> 2);
                int col = nf * 8 + (lane & 3) * 2;
                float* p0 = red1 + ((wid * 32 + row) * 18 + col);
                p0[0] = acc1[mf][nf][0]; p0[1] = acc1[mf][nf][1];
                float* p1 = red1 + ((wid * 32 + row + 8) * 18 + col);
                p1[0] = acc1[mf][nf][2]; p1[1] = acc1[mf][nf][3];
                float* q0 = red2 + ((wid * 32 + row) * 18 + col);
                q0[0] = acc2[mf][nf][0]; q0[1] = acc2[mf][nf][1];
                float* q1 = red2 + ((wid * 32 + row + 8) * 18 + col);
                q1[0] = acc2[mf][nf][2]; q1[1] = acc2[mf][nf][3];
            }
        __syncthreads();

        float h2v = 0.0f;   // for deferred hseq write
        // layer 1 update (threads 0..127), steps 0..2047
        if (tid < 128 && t < Sdim) {
            float di = x_i, df = x_f, dg = x_g, do_ = x_o;
#pragma unroll
            for (int w = 0; w < 8; w++) {
                const float* rr = red1 + (w * 32 + b) * 18;
                di  += rr[0 * 4 + jj];
                df  += rr[1 * 4 + jj];
                dg  += rr[2 * 4 + jj];
                do_ += rr[3 * 4 + jj];
            }
            float ig = 1.0f / (1.0f + __expf(-di));
            float fg = 1.0f / (1.0f + __expf(-df));
            float gg = tanhf(dg);
            float og = 1.0f / (1.0f + __expf(-do_));
            c1 = fg * c1 + ig * gg;
            float h = og * tanhf(c1);
            g_h1b[cur ^ 1][b * Hdim + j0 + jj] = __float2half_rn(h);
        }
        // layer 2 update (threads 128..255), computes h2(t-1), steps 1..2048
        if (tid >= 128 && t >= 1) {
            float di = bias2[0], df = bias2[1], dg = bias2[2], do_ = bias2[3];
#pragma unroll
            for (int w = 0; w < 8; w++) {
                const float* rr = red2 + (w * 32 + b) * 18;
                di  += rr[0 * 4 + jj];
                df  += rr[1 * 4 + jj];
                dg  += rr[2 * 4 + jj];
                do_ += rr[3 * 4 + jj];
            }
            float ig = 1.0f / (1.0f + __expf(-di));
            float fg = 1.0f / (1.0f + __expf(-df));
            float gg = tanhf(dg);
            float og = 1.0f / (1.0f + __expf(-do_));
            c2 = fg * c2 + ig * gg;
            h2v = og * tanhf(c2);
            g_h2b[cur ^ 1][b * Hdim + j0 + jj] = __float2half_rn(h2v);
        }
        __syncthreads();   // h stores done CTA-wide

        // ARRIVE: tid0-only fence (validated grid_barrier release pattern) + striped atomic
        if (tid == 0) {
            __threadfence();
            atomicAdd(&g_cntS[stripe * STRIDEW], 1u);
        }

        // ---- overlap window: output writes + next-step xg prefetch ----
        if (tid >= 128 && t >= 1) {
            hseq[((size_t)b * Sdim + (t - 1)) * Hdim + j0 + jj] = h2v;
            if (t == Sdim) {
                hTo[b * Hdim + j0 + jj] = h2v;
                cTo[b * Hdim + j0 + jj] = c2;
            }
        }
        if (tid < 128 && t + 1 < Sdim) {
            xg_base += (size_t)Bdim * Gdim;
            x_i = __ldg(xg_base + 0 * Hdim);
            x_f = __ldg(xg_base + 1 * Hdim);
            x_g = __ldg(xg_base + 2 * Hdim);
            x_o = __ldg(xg_base + 3 * Hdim);
        }
    }
}

// ---------------- launch ----------------
extern "C" void kernel_launch(void* const* d_in, const int* in_sizes, int n_in,
                              void* d_out, int out_size) {
    (void)in_sizes; (void)n_in;
    const float* X   = (const float*)d_in[0];
    const float* Wih = (const float*)d_in[1];
    const float* Whh = (const float*)d_in[2];
    const float* bih = (const float*)d_in[3];
    const float* bhh = (const float*)d_in[4];
    float* out = (float*)d_out;

    size_t ht_elems = (size_t)Bdim * Sdim * Hdim;
    float* hTo = out + ht_elems;
    float* cTo = hTo + (size_t)Bdim * Hdim;

    const int smem_fused = RED2_OFF + 8 * 32 * 18 * 4;   // 103424
    const int smem_gemm  = 2 * STAGE_B;                  // 81920
    cudaFuncSetAttribute(lstm_fused,
                         cudaFuncAttributeMaxDynamicSharedMemorySize, smem_fused);
    cudaFuncSetAttribute(gemm_mma_kernel,
                         cudaFuncAttributeMaxDynamicSharedMemorySize, smem_gemm);

    conv_w_kernel<<<1024, 256>>>(Wih);                  // layer-0 Wih split
    conv_x_kernel<<<32768, 256>>>(X);

    dim3 ggrid(Gdim / 128, (Sdim * Bdim) / 128);        // (16, 512)
    gemm_mma_kernel<<<ggrid, 256, smem_gemm>>>(bih, bhh);   // layer-1 xg

    lstm_fused<<<NCTA_REC, 256, smem_fused>>>(
        Whh,                                 // Whh layer 1
        Wih + (size_t)Gdim * Hdim,           // Wih layer 2
        Whh + (size_t)Gdim * Hdim,           // Whh layer 2
        bih + Gdim, bhh + Gdim,
        out, hTo, cTo);
}

// round 17
// speedup vs baseline: 2.3975x; 1.0356x over previous
#include <cuda_runtime.h>
#include <cuda_bf16.h>
#include <cuda_fp16.h>
#include <cstdint>

#define Sdim 2048
#define Bdim 32
#define Hdim 512
#define Gdim 2048   // 4*H
#define NCTA_REC 128
#define NSTRIPE 8
#define STRIDEW 64   // unsigned words between stripes (256B)

typedef unsigned long long ull;

// ---------------- scratch (module-load allocated) ----------------
__device__ float g_xg [(size_t)Sdim * Bdim * Gdim];               // layer-1 gates [s*B+b][4H]
__device__ __align__(16) __nv_bfloat16 g_Ahi [(size_t)Sdim * Bdim * Hdim];
__device__ __align__(16) __nv_bfloat16 g_Alo [(size_t)Sdim * Bdim * Hdim];
__device__ __align__(16) __nv_bfloat16 g_Whi [(size_t)Gdim * Hdim];   // layer-0 Wih split
__device__ __align__(16) __nv_bfloat16 g_Wlo [(size_t)Gdim * Hdim];
__device__ __align__(16) __half g_h1b[2][Bdim * Hdim];            // ping-pong h1 (fp16)
__device__ __align__(16) __half g_h2b[2][Bdim * Hdim];            // ping-pong h2 (fp16)
__device__ unsigned g_cnt;    // init barrier
__device__ unsigned g_gen;    // init barrier
__device__ __align__(256) unsigned g_cntS[NSTRIPE * STRIDEW];   // striped arrival counters

// ---------------- PTX helpers ----------------
__device__ __forceinline__ uint32_t smem_u32(const void* p) {
    uint32_t a;
    asm("{ .reg .u64 t; cvta.to.shared.u64 t, %1; cvt.u32.u64 %0, t; }" : "=r"(a) : "l"(p));
    return a;
}
#define CP_ASYNC16(dst, src) \
    asm volatile("cp.async.cg.shared.global [%0], [%1], 16;" :: "r"(dst), "l"(src))
#define CP_COMMIT() asm volatile("cp.async.commit_group;" ::: "memory")
#define CP_WAIT1()  asm volatile("cp.async.wait_group 1;" ::: "memory")
#define CP_WAIT0()  asm volatile("cp.async.wait_group 0;" ::: "memory")

__device__ __forceinline__ void ldm_x4(uint32_t* r, uint32_t addr) {
    asm volatile("ldmatrix.sync.aligned.m8n8.x4.shared.b16 {%0,%1,%2,%3}, [%4];"
                 : "=r"(r[0]), "=r"(r[1]), "=r"(r[2]), "=r"(r[3]) : "r"(addr));
}
__device__ __forceinline__ void mma_bf16(float* d, const uint32_t* a, const uint32_t* b) {
    asm volatile(
        "mma.sync.aligned.m16n8k16.row.col.f32.bf16.bf16.f32 "
        "{%0,%1,%2,%3}, {%4,%5,%6,%7}, {%8,%9}, {%0,%1,%2,%3};"
        : "+f"(d[0]), "+f"(d[1]), "+f"(d[2]), "+f"(d[3])
        : "r"(a[0]), "r"(a[1]), "r"(a[2]), "r"(a[3]), "r"(b[0]), "r"(b[1]));
}
__device__ __forceinline__ void mma_f16(float* d, const uint32_t* a, const uint32_t* b) {
    asm volatile(
        "mma.sync.aligned.m16n8k16.row.col.f32.f16.f16.f32 "
        "{%0,%1,%2,%3}, {%4,%5,%6,%7}, {%8,%9}, {%0,%1,%2,%3};"
        : "+f"(d[0]), "+f"(d[1]), "+f"(d[2]), "+f"(d[3])
        : "r"(a[0]), "r"(a[1]), "r"(a[2]), "r"(a[3]), "r"(b[0]), "r"(b[1]));
}

// ---------------- init grid barrier (validated; replay-safe) ----------------
__device__ __forceinline__ void grid_barrier() {
    __syncthreads();
    if (threadIdx.x == 0) {
        __threadfence();
        unsigned gen = *(volatile unsigned*)&g_gen;
        unsigned old = atomicAdd(&g_cnt, 1u);
        if (old == gridDim.x - 1) {
            atomicExch(&g_cnt, 0u);
            __threadfence();
            atomicAdd(&g_gen, 1u);
        } else {
            while (*(volatile unsigned*)&g_gen == gen) { __nanosleep(32); }
        }
        __threadfence();
    }
    __syncthreads();
}

// ---------------- fp32 -> bf16 hi/lo split (GEMM path) ----------------
__device__ __forceinline__ void split4(float4 v, ull& hi, ull& lo) {
    union { __nv_bfloat16 h[4]; ull u; } H, L;
    float f[4] = {v.x, v.y, v.z, v.w};
#pragma unroll
    for (int i = 0; i < 4; i++) {
        __nv_bfloat16 a = __float2bfloat16_rn(f[i]);
        H.h[i] = a;
        L.h[i] = __float2bfloat16_rn(f[i] - __bfloat162float(a));
    }
    hi = H.u; lo = L.u;
}
// fp32 -> fp16 hi/lo split (recurrence W path)
__device__ __forceinline__ void split4h(float4 v, ull& hi, ull& lo) {
    union { __half h[4]; ull u; } H, L;
    float f[4] = {v.x, v.y, v.z, v.w};
#pragma unroll
    for (int i = 0; i < 4; i++) {
        __half a = __float2half_rn(f[i]);
        H.h[i] = a;
        L.h[i] = __float2half_rn(f[i] - __half2float(a));
    }
    hi = H.u; lo = L.u;
}

// X[b][s][k] -> g_Ahi/g_Alo[(s*B+b)][k]
__global__ __launch_bounds__(256) void conv_x_kernel(const float* __restrict__ X) {
    size_t i = (size_t)blockIdx.x * 256 + threadIdx.x;
    int row = (int)(i >> 7);
    int c4  = (int)(i & 127);
    int b = row & 31, s = row >> 5;
    float4 v = __ldg((const float4*)(X + ((size_t)b * Sdim + s) * Hdim + c4 * 4));
    ull hi, lo;
    split4(v, hi, lo);
    *(ull*)(g_Ahi + (size_t)row * Hdim + c4 * 4) = hi;
    *(ull*)(g_Alo + (size_t)row * Hdim + c4 * 4) = lo;
}

// Wih[0][4H][H] -> g_Whi/g_Wlo (layer 0 only)
__global__ __launch_bounds__(256) void conv_w_kernel(const float* __restrict__ W) {
    size_t i = (size_t)blockIdx.x * 256 + threadIdx.x;   // 262144 float4's
    float4 v = __ldg((const float4*)W + i);
    ull hi, lo;
    split4(v, hi, lo);
    *(ull*)(g_Whi + i * 4) = hi;
    *(ull*)(g_Wlo + i * 4) = lo;
}

// ---------------- mma.sync split-bf16 GEMM (validated R4; layer-0 xg only) ----------------
#define TSTRIDE 80
#define MAT_B   (128 * TSTRIDE)
#define STAGE_B (4 * MAT_B)

__global__ __launch_bounds__(256, 1) void gemm_mma_kernel(
    const float* __restrict__ bih, const float* __restrict__ bhh)
{
    extern __shared__ char smem[];
    uint32_t sb = smem_u32(smem);
    int tid = threadIdx.x, wid = tid >> 5, lane = tid & 31;
    int col0 = blockIdx.x * 128;
    int row0 = blockIdx.y * 128;
    int wm = wid & 1, wn = wid >> 1;

    const __nv_bfloat16* a0p = g_Ahi + (size_t)row0 * Hdim;
    const __nv_bfloat16* a1p = g_Alo + (size_t)row0 * Hdim;
    const __nv_bfloat16* w0p = g_Whi + (size_t)col0 * Hdim;
    const __nv_bfloat16* w1p = g_Wlo + (size_t)col0 * Hdim;

    int ldr  = tid >> 2;
    int ldkc = tid & 3;

#define PREFETCH(stg, k0)                                                         \
    do {                                                                          \
        _Pragma("unroll")                                                         \
        for (int m = 0; m < 4; m++) {                                             \
            const __nv_bfloat16* mp = (m == 0 ? a0p : m == 1 ? a1p :              \
                                       m == 2 ? w0p : w1p);                       \
            _Pragma("unroll")                                                     \
            for (int i = 0; i < 2; i++) {                                         \
                int r = ldr + i * 64;                                             \
                uint32_t dst = sb + (stg) * STAGE_B + m * MAT_B +                 \
                               r * TSTRIDE + ldkc * 16;                           \
                const void* srcp = mp + (size_t)r * Hdim + (k0) + ldkc * 8;       \
                CP_ASYNC16(dst, srcp);                                            \
            }                                                                     \
        }                                                                         \
        CP_COMMIT();                                                              \
    } while (0)

    float acc[4][4][4];
#pragma unroll
    for (int i = 0; i < 4; i++)
#pragma unroll
        for (int j = 0; j < 4; j++)
#pragma unroll
            for (int k = 0; k < 4; k++) acc[i][j][k] = 0.0f;

    PREFETCH(0, 0);
    PREFETCH(1, 32);

    int tile = lane >> 3, trow = lane & 7;

    for (int kt = 0; kt < 16; kt++) {
        if (kt == 15) CP_WAIT0(); else CP_WAIT1();
        __syncthreads();
        uint32_t base = sb + (kt & 1) * STAGE_B;

#pragma unroll
        for (int ks = 0; ks < 2; ks++) {
            uint32_t ahi[4][4], alo[4][4];
#pragma unroll
            for (int mf = 0; mf < 4; mf++) {
                int row = wm * 64 + mf * 16 + (tile & 1) * 8 + trow;
                int col = ks * 16 + (tile >> 1) * 8;
                ldm_x4(ahi[mf], base + 0 * MAT_B + row * TSTRIDE + col * 2);
                ldm_x4(alo[mf], base + 1 * MAT_B + row * TSTRIDE + col * 2);
            }
            uint32_t bhi[4][2], blo[4][2];
#pragma unroll
            for (int p = 0; p < 2; p++) {
                int rn = wn * 32 + p * 16 + (tile >> 1) * 8 + trow;
                int ck = ks * 16 + (tile & 1) * 8;
                uint32_t r4[4];
                ldm_x4(r4, base + 2 * MAT_B + rn * TSTRIDE + ck * 2);
                bhi[2*p][0] = r4[0]; bhi[2*p][1] = r4[1];
                bhi[2*p+1][0] = r4[2]; bhi[2*p+1][1] = r4[3];
                ldm_x4(r4, base + 3 * MAT_B + rn * TSTRIDE + ck * 2);
                blo[2*p][0] = r4[0]; blo[2*p][1] = r4[1];
                blo[2*p+1][0] = r4[2]; blo[2*p+1][1] = r4[3];
            }
#pragma unroll
            for (int mf = 0; mf < 4; mf++)
#pragma unroll
                for (int nf = 0; nf < 4; nf++) {
                    mma_bf16(acc[mf][nf], ahi[mf], bhi[nf]);
                    mma_bf16(acc[mf][nf], ahi[mf], blo[nf]);
                    mma_bf16(acc[mf][nf], alo[mf], bhi[nf]);
                }
        }
        __syncthreads();
        if (kt < 14) PREFETCH(kt & 1, (kt + 2) * 32);
    }

#pragma unroll
    for (int mf = 0; mf < 4; mf++) {
        int r0 = row0 + wm * 64 + mf * 16 + (lane >> 2);
#pragma unroll
        for (int nf = 0; nf < 4; nf++) {
            int cb = col0 + wn * 32 + nf * 8 + 2 * (lane & 3);
            float b0v = __ldg(&bih[cb])     + __ldg(&bhh[cb]);
            float b1v = __ldg(&bih[cb + 1]) + __ldg(&bhh[cb + 1]);
            *(float2*)&g_xg[(size_t)r0 * Gdim + cb] =
                make_float2(acc[mf][nf][0] + b0v, acc[mf][nf][1] + b1v);
            *(float2*)&g_xg[(size_t)(r0 + 8) * Gdim + cb] =
                make_float2(acc[mf][nf][2] + b0v, acc[mf][nf][3] + b1v);
        }
    }
#undef PREFETCH
}

// ---------------- fused 2-layer wavefront recurrence (fp16 h, split-fp16 W) ----------------
// 128 CTAs x 256 threads. CTA owns hidden units j0..j0+3 of BOTH layers.
// Producer-group stripes: CTAs 16s..16s+15 arrive on stripe s. Warp w consumes
// k-cols [64w,64w+64) — produced exactly by stripe w — so each warp gates only
// on its own stripe and flows into staging/MMA independently (skew hiding).
#define RSTRIDE 1040                     // bytes per smem 16-bit row of 512 (+pad)
#define RED1_OFF (64 * RSTRIDE)          // 66560 (sH1+sH2; also W staging at init)
#define RED2_OFF (RED1_OFF + 8*32*18*4)  // +18432

__global__ __launch_bounds__(256, 1) void lstm_fused(
    const float* __restrict__ Whh1, const float* __restrict__ Wih2,
    const float* __restrict__ Whh2,
    const float* __restrict__ bih2, const float* __restrict__ bhh2,
    float* __restrict__ hseq, float* __restrict__ hTo, float* __restrict__ cTo)
{
    extern __shared__ char sm[];
    uint32_t sb = smem_u32(sm);
    uint32_t sH1 = sb;                    // [32 rows] fp16 h1 (init: W-hi staging)
    uint32_t sH2 = sb + 32 * RSTRIDE;     // [32 rows] fp16 h2 (init: W-lo staging)
    float* red1 = (float*)(sm + RED1_OFF);   // [8][32][18]
    float* red2 = (float*)(sm + RED2_OFF);   // [8][32][18]

    int tid = threadIdx.x, wid = tid >> 5, lane = tid & 31;
    int b  = tid & 31;
    int jj = (tid >> 5) & 3;
    int j0 = blockIdx.x * 4;
    int stripe = blockIdx.x >> 4;          // producer group (contiguous 16 CTAs)

    int kbase = wid * 64;
    int tile = lane >> 3, trow = lane & 7;

    // ---- init: load 3 W-frag sets (split fp16) via smem staging ----
    uint32_t w1h[4][2][2],  w1l[4][2][2];
    uint32_t w2ih[4][2][2], w2il[4][2][2];
    uint32_t w2hh[4][2][2], w2hl[4][2][2];

#define LOAD_WFRAGS(Wsrc, Fh, Fl)                                                  \
    do {                                                                           \
        for (int idx = tid; idx < 2048; idx += 256) {                              \
            int r = idx >> 7, c4 = idx & 127;                                      \
            int q = r >> 2, j = r & 3;                                             \
            float4 v = __ldg((const float4*)((Wsrc) +                              \
                        (size_t)(q * Hdim + j0 + j) * Hdim + c4 * 4));             \
            ull hi, lo;                                                            \
            split4h(v, hi, lo);                                                    \
            *(ull*)(sm + r * RSTRIDE + c4 * 8) = hi;                               \
            *(ull*)(sm + 32 * RSTRIDE + r * RSTRIDE + c4 * 8) = lo;                \
        }                                                                          \
        __syncthreads();                                                           \
        _Pragma("unroll")                                                          \
        for (int kt = 0; kt < 4; kt++) {                                           \
            int row = (tile >> 1) * 8 + trow;                                      \
            int col = kbase + kt * 16 + (tile & 1) * 8;                            \
            uint32_t r4[4];                                                        \
            ldm_x4(r4, sH1 + row * RSTRIDE + col * 2);                             \
            Fh[kt][0][0] = r4[0]; Fh[kt][0][1] = r4[1];                            \
            Fh[kt][1][0] = r4[2]; Fh[kt][1][1] = r4[3];                            \
            ldm_x4(r4, sH2 + row * RSTRIDE + col * 2);                             \
            Fl[kt][0][0] = r4[0]; Fl[kt][0][1] = r4[1];                            \
            Fl[kt][1][0] = r4[2]; Fl[kt][1][1] = r4[3];                            \
        }                                                                          \
        __syncthreads();                                                           \
    } while (0)

    LOAD_WFRAGS(Whh1, w1h,  w1l);
    LOAD_WFRAGS(Wih2, w2ih, w2il);
    LOAD_WFRAGS(Whh2, w2hh, w2hl);
#undef LOAD_WFRAGS

    // layer-2 per-thread bias (gate cols q*512 + j0+jj)
    float bias2[4];
#pragma unroll
    for (int q = 0; q < 4; q++)
        bias2[q] = __ldg(&bih2[q * Hdim + j0 + jj]) + __ldg(&bhh2[q * Hdim + j0 + jj]);

    if (blockIdx.x == 0 && tid < NSTRIPE) g_cntS[tid * STRIDEW] = 0u;
    if (tid < 128) {   // h1(-1)=0 in buf[0]; h2(-1)=0 in buf[1]; also h2 buf[0] defined
        g_h1b[0][b * Hdim + j0 + jj] = __float2half(0.0f);
        g_h2b[1][b * Hdim + j0 + jj] = __float2half(0.0f);
        g_h2b[0][b * Hdim + j0 + jj] = __float2half(0.0f);
    }
    grid_barrier();   // zeros + counter resets visible everywhere

    float c1 = 0.0f, c2 = 0.0f;
    const float* xg_base = g_xg + (size_t)b * Gdim + (j0 + jj);
    float x_i = __ldg(xg_base + 0 * Hdim);
    float x_f = __ldg(xg_base + 1 * Hdim);
    float x_g = __ldg(xg_base + 2 * Hdim);
    float x_o = __ldg(xg_base + 3 * Hdim);

    for (int t = 0; t <= Sdim; t++) {
        int cur = t & 1;

        // PER-WARP WAIT: warp w gates only on its producer group (stripe w).
        if (t > 0) {
            if (lane == 0) {
                unsigned target = (unsigned)t * (NCTA_REC / NSTRIPE);
                while (*(volatile unsigned*)&g_cntS[wid * STRIDEW] < target) { }
                __threadfence();   // acquire for this warp's staged reads
            }
            __syncwarp();
        }

        // per-warp stage: own k-slice of h1(t-1), h2(t-2): 2 x 4KB
        {
            const char* s1 = (const char*)g_h1b[cur];
            const char* s2 = (const char*)g_h2b[cur];
            int colbyte = wid * 128;   // 64 fp16
#pragma unroll
            for (int i = 0; i < 8; i++) {
                int c = lane + i * 32;            // 0..255
                int r = c >> 3, ch = c & 7;
                uint32_t off = r * RSTRIDE + colbyte + ch * 16;
                int goff = r * 1024 + colbyte + ch * 16;
                CP_ASYNC16(sH1 + off, s1 + goff);
                CP_ASYNC16(sH2 + off, s2 + goff);
            }
        }
        CP_COMMIT();
        CP_WAIT0();
        __syncwarp();

        // MMA: acc1 = Whh1 @ h1(t-1); acc2 = Wih2 @ h1(t-1) + Whh2 @ h2(t-2)
        float acc1[2][2][4], acc2[2][2][4];
#pragma unroll
        for (int i = 0; i < 2; i++)
#pragma unroll
            for (int j = 0; j < 2; j++)
#pragma unroll
                for (int k = 0; k < 4; k++) { acc1[i][j][k] = 0.0f; acc2[i][j][k] = 0.0f; }

#pragma unroll
        for (int kt = 0; kt < 4; kt++) {
            int colb = kbase + kt * 16 + (tile >> 1) * 8;
            uint32_t a1[2][4], a2[2][4];
#pragma unroll
            for (int mf = 0; mf < 2; mf++) {
                int row = mf * 16 + (tile & 1) * 8 + trow;
                ldm_x4(a1[mf], sH1 + row * RSTRIDE + colb * 2);
                ldm_x4(a2[mf], sH2 + row * RSTRIDE + colb * 2);
            }
#pragma unroll
            for (int mf = 0; mf < 2; mf++)
#pragma unroll
                for (int nf = 0; nf < 2; nf++) {
                    mma_f16(acc1[mf][nf], a1[mf], w1h[kt][nf]);
                    mma_f16(acc1[mf][nf], a1[mf], w1l[kt][nf]);
                    mma_f16(acc2[mf][nf], a1[mf], w2ih[kt][nf]);
                    mma_f16(acc2[mf][nf], a1[mf], w2il[kt][nf]);
                    mma_f16(acc2[mf][nf], a2[mf], w2hh[kt][nf]);
                    mma_f16(acc2[mf][nf], a2[mf], w2hl[kt][nf]);
                }
        }

        // per-warp partials -> red1/red2 [wid][m 0..31][n 0..15]
#pragma unroll
        for (int mf = 0; mf < 2; mf++)
#pragma unroll
            for (int nf = 0; nf < 2; nf++) {
                int row = mf * 16 + (lane >> 2);
                int col = nf * 8 + (lane & 3) * 2;
                float* p0 = red1 + ((wid * 32 + row) * 18 + col);
                p0[0] = acc1[mf][nf][0]; p0[1] = acc1[mf][nf][1];
                float* p1 = red1 + ((wid * 32 + row + 8) * 18 + col);
                p1[0] = acc1[mf][nf][2]; p1[1] = acc1[mf][nf][3];
                float* q0 = red2 + ((wid * 32 + row) * 18 + col);
                q0[0] = acc2[mf][nf][0]; q0[1] = acc2[mf][nf][1];
                float* q1 = red2 + ((wid * 32 + row + 8) * 18 + col);
                q1[0] = acc2[mf][nf][2]; q1[1] = acc2[mf][nf][3];
            }
        __syncthreads();

        float h2v = 0.0f;   // for deferred hseq write
        // layer 1 update (threads 0..127), steps 0..2047
        if (tid < 128 && t < Sdim) {
            float di = x_i, df = x_f, dg = x_g, do_ = x_o;
#pragma unroll
            for (int w = 0; w < 8; w++) {
                const float* rr = red1 + (w * 32 + b) * 18;
                di  += rr[0 * 4 + jj];
                df  += rr[1 * 4 + jj];
                dg  += rr[2 * 4 + jj];
                do_ += rr[3 * 4 + jj];
            }
            float ig = 1.0f / (1.0f + __expf(-di));
            float fg = 1.0f / (1.0f + __expf(-df));
            float gg = tanhf(dg);
            float og = 1.0f / (1.0f + __expf(-do_));
            c1 = fg * c1 + ig * gg;
            float h = og * tanhf(c1);
            g_h1b[cur ^ 1][b * Hdim + j0 + jj] = __float2half_rn(h);
        }
        // layer 2 update (threads 128..255), computes h2(t-1), steps 1..2048
        if (tid >= 128 && t >= 1) {
            float di = bias2[0], df = bias2[1], dg = bias2[2], do_ = bias2[3];
#pragma unroll
            for (int w = 0; w < 8; w++) {
                const float* rr = red2 + (w * 32 + b) * 18;
                di  += rr[0 * 4 + jj];
                df  += rr[1 * 4 + jj];
                dg  += rr[2 * 4 + jj];
                do_ += rr[3 * 4 + jj];
            }
            float ig = 1.0f / (1.0f + __expf(-di));
            float fg = 1.0f / (1.0f + __expf(-df));
            float gg = tanhf(dg);
            float og = 1.0f / (1.0f + __expf(-do_));
            c2 = fg * c2 + ig * gg;
            h2v = og * tanhf(c2);
            g_h2b[cur ^ 1][b * Hdim + j0 + jj] = __float2half_rn(h2v);
        }
        __syncthreads();   // h stores done CTA-wide

        // ARRIVE: tid0-only fence (validated release pattern) + producer-group stripe
        if (tid == 0) {
            __threadfence();
            atomicAdd(&g_cntS[stripe * STRIDEW], 1u);
        }

        // ---- overlap window: output writes + next-step xg prefetch ----
        if (tid >= 128 && t >= 1) {
            hseq[((size_t)b * Sdim + (t - 1)) * Hdim + j0 + jj] = h2v;
            if (t == Sdim) {
                hTo[b * Hdim + j0 + jj] = h2v;
                cTo[b * Hdim + j0 + jj] = c2;
            }
        }
        if (tid < 128 && t + 1 < Sdim) {
            xg_base += (size_t)Bdim * Gdim;
            x_i = __ldg(xg_base + 0 * Hdim);
            x_f = __ldg(xg_base + 1 * Hdim);
            x_g = __ldg(xg_base + 2 * Hdim);
            x_o = __ldg(xg_base + 3 * Hdim);
        }
    }
}

// ---------------- launch ----------------
extern "C" void kernel_launch(void* const* d_in, const int* in_sizes, int n_in,
                              void* d_out, int out_size) {
    (void)in_sizes; (void)n_in;
    const float* X   = (const float*)d_in[0];
    const float* Wih = (const float*)d_in[1];
    const float* Whh = (const float*)d_in[2];
    const float* bih = (const float*)d_in[3];
    const float* bhh = (const float*)d_in[4];
    float* out = (float*)d_out;

    size_t ht_elems = (size_t)Bdim * Sdim * Hdim;
    float* hTo = out + ht_elems;
    float* cTo = hTo + (size_t)Bdim * Hdim;

    const int smem_fused = RED2_OFF + 8 * 32 * 18 * 4;   // 103424
    const int smem_gemm  = 2 * STAGE_B;                  // 81920
    cudaFuncSetAttribute(lstm_fused,
                         cudaFuncAttributeMaxDynamicSharedMemorySize, smem_fused);
    cudaFuncSetAttribute(gemm_mma_kernel,
                         cudaFuncAttributeMaxDynamicSharedMemorySize, smem_gemm);

    conv_w_kernel<<<1024, 256>>>(Wih);                  // layer-0 Wih split
    conv_x_kernel<<<32768, 256>>>(X);

    dim3 ggrid(Gdim / 128, (Sdim * Bdim) / 128);        // (16, 512)
    gemm_mma_kernel<<<ggrid, 256, smem_gemm>>>(bih, bhh);   // layer-1 xg

    lstm_fused<<<NCTA_REC, 256, smem_fused>>>(
        Whh,                                 // Whh layer 1
        Wih + (size_t)Gdim * Hdim,           // Wih layer 2
        Whh + (size_t)Gdim * Hdim,           // Whh layer 2
        bih + Gdim, bhh + Gdim,
        out, hTo, cTo);
}